// round 1
// baseline (speedup 1.0000x reference)
#include <cuda_runtime.h>
#include <cuda_bf16.h>
#include <math.h>

// Problem constants
#define BATCH 2
#define TSEQ  2048
#define CDIM  1024
#define NH    16
#define HD    64
#define THREEC (3*CDIM)
#define MROWS (BATCH*TSEQ)   // 4096

// Scratch (allocation-free rule: __device__ globals)
__device__ float g_qkv[(size_t)MROWS * THREEC];   // [B*T, 3C]  ~50 MB
__device__ float g_att[(size_t)MROWS * CDIM];     // [B*T, C]   ~17 MB

// ---------------------------------------------------------------------------
// SGEMM: C[M,N] = A[M,K] @ B[K,N] + bias[N]   (all row-major, fp32)
// 128x128 block tile, BK=8, 256 threads, 8x8 per-thread tile.
// M,N divisible by 128; K divisible by 8. No bounds checks needed here.
// ---------------------------------------------------------------------------
__global__ __launch_bounds__(256) void sgemm128(
    const float* __restrict__ A, const float* __restrict__ B,
    const float* __restrict__ bias, float* __restrict__ C,
    int M, int N, int K)
{
    constexpr int BM = 128, BN = 128, BK = 8, TM = 8, TN = 8;
    __shared__ float As[BK][BM];
    __shared__ float Bs[BK][BN];

    const int tid = threadIdx.x;
    const int tx = tid & 15;        // 0..15
    const int ty = tid >> 4;        // 0..15
    const int row0 = blockIdx.y * BM;
    const int col0 = blockIdx.x * BN;

    // A-tile load map: 128 rows x 8 cols; one float4 per thread
    const int aRow = tid >> 1;           // 0..127
    const int aCol = (tid & 1) << 2;     // 0 or 4
    // B-tile load map: 8 rows x 128 cols; one float4 per thread
    const int bRow = tid >> 5;           // 0..7
    const int bCol = (tid & 31) << 2;    // 0..124

    const float* Aptr = A + (size_t)(row0 + aRow) * K + aCol;
    const float* Bptr = B + (size_t)bRow * N + col0 + bCol;

    float acc[TM][TN];
    #pragma unroll
    for (int i = 0; i < TM; i++)
        #pragma unroll
        for (int j = 0; j < TN; j++) acc[i][j] = 0.f;

    for (int k0 = 0; k0 < K; k0 += BK) {
        float4 av = *reinterpret_cast<const float4*>(Aptr + k0);
        float4 bv = *reinterpret_cast<const float4*>(Bptr + (size_t)k0 * N);
        As[aCol + 0][aRow] = av.x;
        As[aCol + 1][aRow] = av.y;
        As[aCol + 2][aRow] = av.z;
        As[aCol + 3][aRow] = av.w;
        *reinterpret_cast<float4*>(&Bs[bRow][bCol]) = bv;
        __syncthreads();

        #pragma unroll
        for (int k = 0; k < BK; k++) {
            float af[TM], bf[TN];
            #pragma unroll
            for (int i = 0; i < TM; i++) af[i] = As[k][ty * TM + i];
            #pragma unroll
            for (int j = 0; j < TN; j++) bf[j] = Bs[k][tx * TN + j];
            #pragma unroll
            for (int i = 0; i < TM; i++)
                #pragma unroll
                for (int j = 0; j < TN; j++)
                    acc[i][j] = fmaf(af[i], bf[j], acc[i][j]);
        }
        __syncthreads();
    }

    // Epilogue: add bias, float4 stores
    #pragma unroll
    for (int i = 0; i < TM; i++) {
        const int r = row0 + ty * TM + i;
        #pragma unroll
        for (int j = 0; j < TN; j += 4) {
            const int c = col0 + tx * TN + j;
            float4 o;
            o.x = acc[i][j + 0] + bias[c + 0];
            o.y = acc[i][j + 1] + bias[c + 1];
            o.z = acc[i][j + 2] + bias[c + 2];
            o.w = acc[i][j + 3] + bias[c + 3];
            *reinterpret_cast<float4*>(&C[(size_t)r * N + c]) = o;
        }
    }
}

// ---------------------------------------------------------------------------
// Flash-style causal attention, fp32.
// Grid: (qt=32, h=16, b=2), 256 threads.
// Per block: 64 q-rows. Loops over 64-col k-tiles up to the diagonal only.
// Smem: Qs[64][68], KPs[64][68] (K tile, later reused for P), Vs[64][68].
// Thread (ty,tx) owns a 4x4 micro-tile of the 64x64 S/P tile and a 4x4
// micro-tile of the 64x64 O tile. Row reductions via 16-lane shuffles.
// ---------------------------------------------------------------------------
#define BQ 64
#define BKT 64
#define SSTR 68
#define ATTN_SMEM (3 * BQ * SSTR * (int)sizeof(float))

__global__ __launch_bounds__(256) void attn_kernel(
    const float* __restrict__ qkv, float* __restrict__ out)
{
    extern __shared__ float sm[];
    float* Qs  = sm;                  // [64][SSTR]
    float* KPs = sm + BQ * SSTR;      // [64][SSTR] : K tile, then P tile
    float* Vs  = sm + 2 * BQ * SSTR;  // [64][SSTR]

    const int qt  = blockIdx.x;
    const int h   = blockIdx.y;
    const int b   = blockIdx.z;
    const int tid = threadIdx.x;
    const int tx  = tid & 15;
    const int ty  = tid >> 4;
    const int q0  = qt * BQ;

    const size_t base = (size_t)b * TSEQ * THREEC;
    const int qoff = h * HD;
    const int koff = CDIM + h * HD;
    const int voff = 2 * CDIM + h * HD;

    // Load Q tile (64 rows x 64 cols), 16 elems/thread, coalesced.
    #pragma unroll
    for (int e = 0; e < (BQ * HD) / 256; e++) {
        int lin = e * 256 + tid;
        int r = lin >> 6, c = lin & 63;
        Qs[r * SSTR + c] = qkv[base + (size_t)(q0 + r) * THREEC + qoff + c];
    }

    float m_i[4], l_i[4], o[4][4];
    #pragma unroll
    for (int i = 0; i < 4; i++) {
        m_i[i] = -3.0e38f;
        l_i[i] = 0.f;
        #pragma unroll
        for (int j = 0; j < 4; j++) o[i][j] = 0.f;
    }

    const float scale = 0.125f;   // 1/sqrt(64)

    for (int kt = 0; kt <= qt; kt++) {
        const int k0 = kt * BKT;
        __syncthreads();  // prev-iter PV done (and Q-load complete on iter 0)

        // Load K, V tiles
        #pragma unroll
        for (int e = 0; e < (BKT * HD) / 256; e++) {
            int lin = e * 256 + tid;
            int r = lin >> 6, c = lin & 63;
            const size_t rowb = base + (size_t)(k0 + r) * THREEC;
            KPs[r * SSTR + c] = qkv[rowb + koff + c];
            Vs[r * SSTR + c]  = qkv[rowb + voff + c];
        }
        __syncthreads();

        // S = Q @ K^T  (4x4 per thread)
        float s[4][4];
        #pragma unroll
        for (int i = 0; i < 4; i++)
            #pragma unroll
            for (int j = 0; j < 4; j++) s[i][j] = 0.f;

        #pragma unroll 8
        for (int d = 0; d < HD; d++) {
            float qf[4], kf[4];
            #pragma unroll
            for (int i = 0; i < 4; i++) qf[i] = Qs[(ty * 4 + i) * SSTR + d];
            #pragma unroll
            for (int j = 0; j < 4; j++) kf[j] = KPs[(tx * 4 + j) * SSTR + d];
            #pragma unroll
            for (int i = 0; i < 4; i++)
                #pragma unroll
                for (int j = 0; j < 4; j++)
                    s[i][j] = fmaf(qf[i], kf[j], s[i][j]);
        }

        // Scale + causal mask (only the diagonal tile needs masking)
        if (kt == qt) {
            #pragma unroll
            for (int i = 0; i < 4; i++) {
                const int gr = q0 + ty * 4 + i;
                #pragma unroll
                for (int j = 0; j < 4; j++) {
                    const int gc = k0 + tx * 4 + j;
                    s[i][j] = (gc <= gr) ? s[i][j] * scale : -3.0e38f;
                }
            }
        } else {
            #pragma unroll
            for (int i = 0; i < 4; i++)
                #pragma unroll
                for (int j = 0; j < 4; j++) s[i][j] *= scale;
        }

        // Online softmax (row reductions across the 16 tx lanes)
        float mnew[4], rs[4];
        #pragma unroll
        for (int i = 0; i < 4; i++) {
            float rm = fmaxf(fmaxf(s[i][0], s[i][1]), fmaxf(s[i][2], s[i][3]));
            rm = fmaxf(rm, __shfl_xor_sync(0xffffffffu, rm, 1));
            rm = fmaxf(rm, __shfl_xor_sync(0xffffffffu, rm, 2));
            rm = fmaxf(rm, __shfl_xor_sync(0xffffffffu, rm, 4));
            rm = fmaxf(rm, __shfl_xor_sync(0xffffffffu, rm, 8));
            mnew[i] = fmaxf(m_i[i], rm);
            float sum = 0.f;
            #pragma unroll
            for (int j = 0; j < 4; j++) {
                s[i][j] = __expf(s[i][j] - mnew[i]);
                sum += s[i][j];
            }
            sum += __shfl_xor_sync(0xffffffffu, sum, 1);
            sum += __shfl_xor_sync(0xffffffffu, sum, 2);
            sum += __shfl_xor_sync(0xffffffffu, sum, 4);
            sum += __shfl_xor_sync(0xffffffffu, sum, 8);
            rs[i] = sum;
        }

        __syncthreads();  // everyone finished reading the K tile

        // Rescale state, write P into KPs
        #pragma unroll
        for (int i = 0; i < 4; i++) {
            const float alpha = __expf(m_i[i] - mnew[i]);
            l_i[i] = l_i[i] * alpha + rs[i];
            m_i[i] = mnew[i];
            #pragma unroll
            for (int j = 0; j < 4; j++) {
                o[i][j] *= alpha;
                KPs[(ty * 4 + i) * SSTR + tx * 4 + j] = s[i][j];
            }
        }
        __syncthreads();

        // O += P @ V
        #pragma unroll 8
        for (int c = 0; c < BKT; c++) {
            float pf[4], vf[4];
            #pragma unroll
            for (int i = 0; i < 4; i++) pf[i] = KPs[(ty * 4 + i) * SSTR + c];
            #pragma unroll
            for (int j = 0; j < 4; j++) vf[j] = Vs[c * SSTR + tx * 4 + j];
            #pragma unroll
            for (int i = 0; i < 4; i++)
                #pragma unroll
                for (int j = 0; j < 4; j++)
                    o[i][j] = fmaf(pf[i], vf[j], o[i][j]);
        }
    }

    // Epilogue: normalize and write to [B,T,C] layout (head-interleaved)
    const size_t obase = (size_t)b * TSEQ * CDIM + qoff;
    #pragma unroll
    for (int i = 0; i < 4; i++) {
        const float inv = 1.0f / l_i[i];
        const int r = q0 + ty * 4 + i;
        #pragma unroll
        for (int j = 0; j < 4; j++)
            out[obase + (size_t)r * CDIM + tx * 4 + j] = o[i][j] * inv;
    }
}

// ---------------------------------------------------------------------------
// Launch
// ---------------------------------------------------------------------------
extern "C" void kernel_launch(void* const* d_in, const int* in_sizes, int n_in,
                              void* d_out, int out_size)
{
    const float* x     = (const float*)d_in[0];
    const float* Wqkv  = (const float*)d_in[1];
    const float* bqkv  = (const float*)d_in[2];
    const float* Wproj = (const float*)d_in[3];
    const float* bproj = (const float*)d_in[4];
    float* out = (float*)d_out;

    float *qkv, *att;
    cudaGetSymbolAddress((void**)&qkv, g_qkv);
    cudaGetSymbolAddress((void**)&att, g_att);

    cudaFuncSetAttribute(attn_kernel,
                         cudaFuncAttributeMaxDynamicSharedMemorySize, ATTN_SMEM);

    // 1) QKV GEMM: [4096,1024] @ [1024,3072] + bqkv
    dim3 g1(THREEC / 128, MROWS / 128);
    sgemm128<<<g1, 256>>>(x, Wqkv, bqkv, qkv, MROWS, THREEC, CDIM);

    // 2) Causal attention
    dim3 g2(TSEQ / BQ, NH, BATCH);
    attn_kernel<<<g2, 256, ATTN_SMEM>>>(qkv, att);

    // 3) Output projection: [4096,1024] @ [1024,1024] + bproj
    dim3 g3(CDIM / 128, MROWS / 128);
    sgemm128<<<g3, 256>>>(att, Wproj, bproj, out, MROWS, CDIM, CDIM);
}

// round 3
// speedup vs baseline: 1.2814x; 1.2814x over previous
#include <cuda_runtime.h>
#include <cuda_bf16.h>
#include <math.h>
#include <cstdint>

// Problem constants
#define BATCH 2
#define TSEQ  2048
#define CDIM  1024
#define NH    16
#define HD    64
#define THREEC (3*CDIM)
#define MROWS (BATCH*TSEQ)   // 4096
#define K3    (3*CDIM)       // packed split-K = 3072

// ---------------------------------------------------------------------------
// Scratch (__device__ globals; allocation-free rule)
// ---------------------------------------------------------------------------
__device__ float         g_qkv[(size_t)MROWS * THREEC];    // [B*T, 3C] fp32
__device__ float         g_att[(size_t)MROWS * CDIM];      // [B*T, C]  fp32
__device__ __nv_bfloat16 g_ahat[(size_t)MROWS * K3];       // packed activations
__device__ __nv_bfloat16 g_bqkv[(size_t)THREEC * K3];      // packed Wqkv^T
__device__ __nv_bfloat16 g_bproj[(size_t)CDIM * K3];       // packed Wproj^T

// ---------------------------------------------------------------------------
// Helpers (base-ISA only: cp.async / ldmatrix / mma.sync — no tcgen05)
// ---------------------------------------------------------------------------
__device__ __forceinline__ uint32_t smem_u32(const void* p) {
    uint32_t a;
    asm("{ .reg .u64 t; cvta.to.shared.u64 t, %1; cvt.u32.u64 %0, t; }"
        : "=r"(a) : "l"(p));
    return a;
}
#define CP_ASYNC16(smaddr, gptr) \
    asm volatile("cp.async.cg.shared.global [%0], [%1], 16;" \
                 :: "r"(smaddr), "l"(gptr))
#define CP_COMMIT() asm volatile("cp.async.commit_group;" ::: "memory")
#define CP_WAIT(n)  asm volatile("cp.async.wait_group %0;" :: "n"(n) : "memory")

#define LDSM_X4(r0, r1, r2, r3, addr) \
    asm volatile("ldmatrix.sync.aligned.m8n8.x4.shared.b16 {%0,%1,%2,%3}, [%4];" \
                 : "=r"(r0), "=r"(r1), "=r"(r2), "=r"(r3) : "r"(addr))

#define MMA_BF16(c0, c1, c2, c3, a0, a1, a2, a3, b0, b1) \
    asm volatile("mma.sync.aligned.m16n8k16.row.col.f32.bf16.bf16.f32 " \
                 "{%0,%1,%2,%3}, {%4,%5,%6,%7}, {%8,%9}, {%0,%1,%2,%3};" \
                 : "+f"(c0), "+f"(c1), "+f"(c2), "+f"(c3) \
                 : "r"(a0), "r"(a1), "r"(a2), "r"(a3), "r"(b0), "r"(b1))

// ---------------------------------------------------------------------------
// Split-convert activations: A[M,K] fp32 -> Ahat[M,3K] bf16 = [hi | hi | lo]
// ---------------------------------------------------------------------------
__global__ void convert_split_act(const float* __restrict__ in,
                                  __nv_bfloat16* __restrict__ out, int MK, int K)
{
    int idx = blockIdx.x * blockDim.x + threadIdx.x;
    if (idx >= MK) return;
    int m = idx / K, k = idx - m * K;
    float v = in[idx];
    __nv_bfloat16 hi = __float2bfloat16(v);
    __nv_bfloat16 lo = __float2bfloat16(v - __bfloat162float(hi));
    size_t base = (size_t)m * (3 * K);
    out[base + k]         = hi;
    out[base + K + k]     = hi;
    out[base + 2 * K + k] = lo;
}

// ---------------------------------------------------------------------------
// Transpose + split-convert weights: W[K,N] fp32 -> Bhat[N,3K] bf16 = [hi|lo|hi]
// ---------------------------------------------------------------------------
__global__ void convert_split_wT(const float* __restrict__ W,
                                 __nv_bfloat16* __restrict__ out, int K, int N)
{
    __shared__ float t[32][33];
    const int tx = threadIdx.x, ty = threadIdx.y;   // block (32, 8)
    const int n0 = blockIdx.x * 32, k0 = blockIdx.y * 32;
    #pragma unroll
    for (int j = 0; j < 4; j++)
        t[ty + j * 8][tx] = W[(size_t)(k0 + ty + j * 8) * N + n0 + tx];
    __syncthreads();
    #pragma unroll
    for (int j = 0; j < 4; j++) {
        const int nn = ty + j * 8;
        float v = t[tx][nn];
        __nv_bfloat16 hi = __float2bfloat16(v);
        __nv_bfloat16 lo = __float2bfloat16(v - __bfloat162float(hi));
        size_t base = (size_t)(n0 + nn) * (3 * K) + k0 + tx;
        out[base]         = hi;
        out[base + K]     = lo;
        out[base + 2 * K] = hi;
    }
}

// ---------------------------------------------------------------------------
// mma.sync bf16 GEMM: C[M,N] = Ahat[M,K3] · Bhat[N,K3]^T + bias
// 128x128 CTA tile, BK=32, 256 threads (8 warps, warp tile 32x64),
// double-buffered cp.async, ldmatrix operands, padded smem (40 elem = 80B rows).
// ---------------------------------------------------------------------------
#define GBK   32
#define NSTG  (K3 / GBK)          // 96
#define APAD  40                   // elements per smem row (80 bytes)
#define TILE_ELEMS (128 * APAD)    // per buffer

__global__ __launch_bounds__(256) void gemm_mma(
    const __nv_bfloat16* __restrict__ A,   // [M, K3]
    const __nv_bfloat16* __restrict__ B,   // [N, K3]
    const float* __restrict__ bias,
    float* __restrict__ C, int M, int N)
{
    __shared__ __align__(16) __nv_bfloat16 smA[2][TILE_ELEMS];
    __shared__ __align__(16) __nv_bfloat16 smB[2][TILE_ELEMS];

    const int tid  = threadIdx.x;
    const int wid  = tid >> 5;
    const int lane = tid & 31;
    const int wm   = wid & 3;      // warp row: 4 x 32 rows
    const int wn   = wid >> 2;     // warp col: 2 x 64 cols
    const int row0 = blockIdx.y * 128;
    const int col0 = blockIdx.x * 128;

    const uint32_t smA_b = smem_u32(smA);
    const uint32_t smB_b = smem_u32(smB);
    const uint32_t BUFB  = TILE_ELEMS * 2;   // bytes per buffer

    // cp.async load map: 512 16B-chunks per tile; 2 per thread per tile.
    const int ldr = tid >> 1;                 // unused placeholder
    (void)ldr;

    const __nv_bfloat16* Arow = A + (size_t)row0 * K3;
    const __nv_bfloat16* Brow = B + (size_t)col0 * K3;

    auto load_stage = [&](int s, int buf) {
        const int k0 = s * GBK;
        #pragma unroll
        for (int i = 0; i < 2; i++) {
            const int idx = i * 256 + tid;    // 0..511
            const int r   = idx >> 2;         // 0..127
            const int c   = idx & 3;          // 16B chunk within row
            const uint32_t so = (uint32_t)(r * 80 + c * 16);
            CP_ASYNC16(smA_b + buf * BUFB + so, Arow + (size_t)r * K3 + k0 + c * 8);
            CP_ASYNC16(smB_b + buf * BUFB + so, Brow + (size_t)r * K3 + k0 + c * 8);
        }
    };

    float acc[2][8][4];
    #pragma unroll
    for (int i = 0; i < 2; i++)
        #pragma unroll
        for (int j = 0; j < 8; j++)
            #pragma unroll
            for (int k = 0; k < 4; k++) acc[i][j][k] = 0.f;

    // lane-derived ldmatrix offsets (bytes)
    const int lrow = lane & 15;
    const int lcol = (lane >> 4) << 4;    // 0 or 16 bytes

    load_stage(0, 0);
    CP_COMMIT();

    for (int s = 0; s < NSTG; s++) {
        const int buf = s & 1;
        if (s + 1 < NSTG) {
            load_stage(s + 1, (s + 1) & 1);
            CP_COMMIT();
            CP_WAIT(1);
        } else {
            CP_WAIT(0);
        }
        __syncthreads();

        const uint32_t aB = smA_b + buf * BUFB;
        const uint32_t bB = smB_b + buf * BUFB;

        #pragma unroll
        for (int ks = 0; ks < 2; ks++) {
            uint32_t a[2][4], bf[4][4];
            #pragma unroll
            for (int fm = 0; fm < 2; fm++) {
                const uint32_t ad = aB +
                    (uint32_t)((wm * 32 + fm * 16 + lrow) * 80 + ks * 32) + lcol;
                LDSM_X4(a[fm][0], a[fm][1], a[fm][2], a[fm][3], ad);
            }
            #pragma unroll
            for (int g = 0; g < 4; g++) {
                const uint32_t bd = bB +
                    (uint32_t)((wn * 64 + g * 16 + lrow) * 80 + ks * 32) + lcol;
                LDSM_X4(bf[g][0], bf[g][1], bf[g][2], bf[g][3], bd);
            }
            #pragma unroll
            for (int fm = 0; fm < 2; fm++)
                #pragma unroll
                for (int fn = 0; fn < 8; fn++) {
                    const int g = fn >> 1, h = fn & 1;
                    MMA_BF16(acc[fm][fn][0], acc[fm][fn][1],
                             acc[fm][fn][2], acc[fm][fn][3],
                             a[fm][0], a[fm][1], a[fm][2], a[fm][3],
                             bf[g][h], bf[g][2 + h]);
                }
        }
        __syncthreads();
    }

    // Epilogue: C fragment layout: rows lane/4 and lane/4+8; cols 2*(lane%4)
    const int erow = lane >> 2;
    const int ecol = (lane & 3) << 1;
    #pragma unroll
    for (int fm = 0; fm < 2; fm++) {
        const int r0g = row0 + wm * 32 + fm * 16 + erow;
        #pragma unroll
        for (int fn = 0; fn < 8; fn++) {
            const int cg = col0 + wn * 64 + fn * 8 + ecol;
            const float b0 = bias[cg], b1 = bias[cg + 1];
            float2 v0 = make_float2(acc[fm][fn][0] + b0, acc[fm][fn][1] + b1);
            float2 v1 = make_float2(acc[fm][fn][2] + b0, acc[fm][fn][3] + b1);
            *reinterpret_cast<float2*>(&C[(size_t)r0g * N + cg]) = v0;
            *reinterpret_cast<float2*>(&C[(size_t)(r0g + 8) * N + cg]) = v1;
        }
    }
}

// ---------------------------------------------------------------------------
// Flash-style causal attention, fp32 SIMT (unchanged; known-good).
// ---------------------------------------------------------------------------
#define BQ 64
#define BKT 64
#define SSTR 68
#define ATTN_SMEM (3 * BQ * SSTR * (int)sizeof(float))

__global__ __launch_bounds__(256) void attn_kernel(
    const float* __restrict__ qkv, float* __restrict__ out)
{
    extern __shared__ float sm[];
    float* Qs  = sm;
    float* KPs = sm + BQ * SSTR;
    float* Vs  = sm + 2 * BQ * SSTR;

    const int qt  = blockIdx.x;
    const int h   = blockIdx.y;
    const int b   = blockIdx.z;
    const int tid = threadIdx.x;
    const int tx  = tid & 15;
    const int ty  = tid >> 4;
    const int q0  = qt * BQ;

    const size_t base = (size_t)b * TSEQ * THREEC;
    const int qoff = h * HD;
    const int koff = CDIM + h * HD;
    const int voff = 2 * CDIM + h * HD;

    #pragma unroll
    for (int e = 0; e < (BQ * HD) / 256; e++) {
        int lin = e * 256 + tid;
        int r = lin >> 6, c = lin & 63;
        Qs[r * SSTR + c] = qkv[base + (size_t)(q0 + r) * THREEC + qoff + c];
    }

    float m_i[4], l_i[4], o[4][4];
    #pragma unroll
    for (int i = 0; i < 4; i++) {
        m_i[i] = -3.0e38f;
        l_i[i] = 0.f;
        #pragma unroll
        for (int j = 0; j < 4; j++) o[i][j] = 0.f;
    }

    const float scale = 0.125f;

    for (int kt = 0; kt <= qt; kt++) {
        const int k0 = kt * BKT;
        __syncthreads();

        #pragma unroll
        for (int e = 0; e < (BKT * HD) / 256; e++) {
            int lin = e * 256 + tid;
            int r = lin >> 6, c = lin & 63;
            const size_t rowb = base + (size_t)(k0 + r) * THREEC;
            KPs[r * SSTR + c] = qkv[rowb + koff + c];
            Vs[r * SSTR + c]  = qkv[rowb + voff + c];
        }
        __syncthreads();

        float s[4][4];
        #pragma unroll
        for (int i = 0; i < 4; i++)
            #pragma unroll
            for (int j = 0; j < 4; j++) s[i][j] = 0.f;

        #pragma unroll 8
        for (int d = 0; d < HD; d++) {
            float qf[4], kf[4];
            #pragma unroll
            for (int i = 0; i < 4; i++) qf[i] = Qs[(ty * 4 + i) * SSTR + d];
            #pragma unroll
            for (int j = 0; j < 4; j++) kf[j] = KPs[(tx * 4 + j) * SSTR + d];
            #pragma unroll
            for (int i = 0; i < 4; i++)
                #pragma unroll
                for (int j = 0; j < 4; j++)
                    s[i][j] = fmaf(qf[i], kf[j], s[i][j]);
        }

        if (kt == qt) {
            #pragma unroll
            for (int i = 0; i < 4; i++) {
                const int gr = q0 + ty * 4 + i;
                #pragma unroll
                for (int j = 0; j < 4; j++) {
                    const int gc = k0 + tx * 4 + j;
                    s[i][j] = (gc <= gr) ? s[i][j] * scale : -3.0e38f;
                }
            }
        } else {
            #pragma unroll
            for (int i = 0; i < 4; i++)
                #pragma unroll
                for (int j = 0; j < 4; j++) s[i][j] *= scale;
        }

        float mnew[4], rs[4];
        #pragma unroll
        for (int i = 0; i < 4; i++) {
            float rm = fmaxf(fmaxf(s[i][0], s[i][1]), fmaxf(s[i][2], s[i][3]));
            rm = fmaxf(rm, __shfl_xor_sync(0xffffffffu, rm, 1));
            rm = fmaxf(rm, __shfl_xor_sync(0xffffffffu, rm, 2));
            rm = fmaxf(rm, __shfl_xor_sync(0xffffffffu, rm, 4));
            rm = fmaxf(rm, __shfl_xor_sync(0xffffffffu, rm, 8));
            mnew[i] = fmaxf(m_i[i], rm);
            float sum = 0.f;
            #pragma unroll
            for (int j = 0; j < 4; j++) {
                s[i][j] = __expf(s[i][j] - mnew[i]);
                sum += s[i][j];
            }
            sum += __shfl_xor_sync(0xffffffffu, sum, 1);
            sum += __shfl_xor_sync(0xffffffffu, sum, 2);
            sum += __shfl_xor_sync(0xffffffffu, sum, 4);
            sum += __shfl_xor_sync(0xffffffffu, sum, 8);
            rs[i] = sum;
        }

        __syncthreads();

        #pragma unroll
        for (int i = 0; i < 4; i++) {
            const float alpha = __expf(m_i[i] - mnew[i]);
            l_i[i] = l_i[i] * alpha + rs[i];
            m_i[i] = mnew[i];
            #pragma unroll
            for (int j = 0; j < 4; j++) {
                o[i][j] *= alpha;
                KPs[(ty * 4 + i) * SSTR + tx * 4 + j] = s[i][j];
            }
        }
        __syncthreads();

        #pragma unroll 8
        for (int c = 0; c < BKT; c++) {
            float pf[4], vf[4];
            #pragma unroll
            for (int i = 0; i < 4; i++) pf[i] = KPs[(ty * 4 + i) * SSTR + c];
            #pragma unroll
            for (int j = 0; j < 4; j++) vf[j] = Vs[c * SSTR + tx * 4 + j];
            #pragma unroll
            for (int i = 0; i < 4; i++)
                #pragma unroll
                for (int j = 0; j < 4; j++)
                    o[i][j] = fmaf(pf[i], vf[j], o[i][j]);
        }
    }

    const size_t obase = (size_t)b * TSEQ * CDIM + qoff;
    #pragma unroll
    for (int i = 0; i < 4; i++) {
        const float inv = 1.0f / l_i[i];
        const int r = q0 + ty * 4 + i;
        #pragma unroll
        for (int j = 0; j < 4; j++)
            out[obase + (size_t)r * CDIM + tx * 4 + j] = o[i][j] * inv;
    }
}

// ---------------------------------------------------------------------------
// Launch
// ---------------------------------------------------------------------------
extern "C" void kernel_launch(void* const* d_in, const int* in_sizes, int n_in,
                              void* d_out, int out_size)
{
    const float* x     = (const float*)d_in[0];
    const float* Wqkv  = (const float*)d_in[1];
    const float* bqkv  = (const float*)d_in[2];
    const float* Wproj = (const float*)d_in[3];
    const float* bproj = (const float*)d_in[4];
    float* out = (float*)d_out;

    float *qkv, *att;
    __nv_bfloat16 *ahat, *bqkvp, *bprojp;
    cudaGetSymbolAddress((void**)&qkv,    g_qkv);
    cudaGetSymbolAddress((void**)&att,    g_att);
    cudaGetSymbolAddress((void**)&ahat,   g_ahat);
    cudaGetSymbolAddress((void**)&bqkvp,  g_bqkv);
    cudaGetSymbolAddress((void**)&bprojp, g_bproj);

    cudaFuncSetAttribute(attn_kernel,
                         cudaFuncAttributeMaxDynamicSharedMemorySize, ATTN_SMEM);

    // Pack weights (every call; cheap)
    {
        dim3 b(32, 8);
        convert_split_wT<<<dim3(THREEC / 32, CDIM / 32), b>>>(Wqkv, bqkvp, CDIM, THREEC);
        convert_split_wT<<<dim3(CDIM / 32, CDIM / 32), b>>>(Wproj, bprojp, CDIM, CDIM);
    }

    // 1) Pack x and run QKV GEMM
    convert_split_act<<<(MROWS * CDIM + 255) / 256, 256>>>(x, ahat, MROWS * CDIM, CDIM);
    gemm_mma<<<dim3(THREEC / 128, MROWS / 128), 256>>>(ahat, bqkvp, bqkv, qkv, MROWS, THREEC);

    // 2) Causal attention (fp32)
    attn_kernel<<<dim3(TSEQ / BQ, NH, BATCH), 256, ATTN_SMEM>>>(qkv, att);

    // 3) Pack att and run output projection
    convert_split_act<<<(MROWS * CDIM + 255) / 256, 256>>>(att, ahat, MROWS * CDIM, CDIM);
    gemm_mma<<<dim3(CDIM / 128, MROWS / 128), 256>>>(ahat, bprojp, bproj, out, MROWS, CDIM);
}

// round 4
// speedup vs baseline: 2.2059x; 1.7215x over previous
#include <cuda_runtime.h>
#include <cuda_bf16.h>
#include <math.h>
#include <cstdint>

// Problem constants
#define BATCH 2
#define TSEQ  2048
#define CDIM  1024
#define NH    16
#define HD    64
#define THREEC (3*CDIM)
#define MROWS (BATCH*TSEQ)   // 4096
#define K3    (3*CDIM)       // packed split-K = 3072

// ---------------------------------------------------------------------------
// Scratch (__device__ globals; allocation-free rule)
// ---------------------------------------------------------------------------
__device__ float         g_qkv[(size_t)MROWS * THREEC];    // [B*T, 3C] fp32
__device__ float         g_att[(size_t)MROWS * CDIM];      // [B*T, C]  fp32
__device__ __nv_bfloat16 g_ahat[(size_t)MROWS * K3];       // packed activations
__device__ __nv_bfloat16 g_bqkv[(size_t)THREEC * K3];      // packed Wqkv^T
__device__ __nv_bfloat16 g_bproj[(size_t)CDIM * K3];       // packed Wproj^T

// ---------------------------------------------------------------------------
// Helpers (base-ISA only: cp.async / ldmatrix / mma.sync)
// ---------------------------------------------------------------------------
__device__ __forceinline__ uint32_t smem_u32(const void* p) {
    uint32_t a;
    asm("{ .reg .u64 t; cvta.to.shared.u64 t, %1; cvt.u32.u64 %0, t; }"
        : "=r"(a) : "l"(p));
    return a;
}
#define CP_ASYNC16(smaddr, gptr) \
    asm volatile("cp.async.cg.shared.global [%0], [%1], 16;" \
                 :: "r"(smaddr), "l"(gptr))
#define CP_COMMIT() asm volatile("cp.async.commit_group;" ::: "memory")
#define CP_WAIT(n)  asm volatile("cp.async.wait_group %0;" :: "n"(n) : "memory")

#define LDSM_X4(r0, r1, r2, r3, addr) \
    asm volatile("ldmatrix.sync.aligned.m8n8.x4.shared.b16 {%0,%1,%2,%3}, [%4];" \
                 : "=r"(r0), "=r"(r1), "=r"(r2), "=r"(r3) : "r"(addr))

#define MMA_BF16(c0, c1, c2, c3, a0, a1, a2, a3, b0, b1) \
    asm volatile("mma.sync.aligned.m16n8k16.row.col.f32.bf16.bf16.f32 " \
                 "{%0,%1,%2,%3}, {%4,%5,%6,%7}, {%8,%9}, {%0,%1,%2,%3};" \
                 : "+f"(c0), "+f"(c1), "+f"(c2), "+f"(c3) \
                 : "r"(a0), "r"(a1), "r"(a2), "r"(a3), "r"(b0), "r"(b1))

__device__ __forceinline__ uint32_t pack_bf16(float x, float y) {
    __nv_bfloat162 h = __floats2bfloat162_rn(x, y);
    return *reinterpret_cast<uint32_t*>(&h);
}

// ---------------------------------------------------------------------------
// Split-convert activations: A[M,K] fp32 -> Ahat[M,3K] bf16 = [hi | hi | lo]
// ---------------------------------------------------------------------------
__global__ void convert_split_act(const float* __restrict__ in,
                                  __nv_bfloat16* __restrict__ out, int MK, int K)
{
    int idx = blockIdx.x * blockDim.x + threadIdx.x;
    if (idx >= MK) return;
    int m = idx / K, k = idx - m * K;
    float v = in[idx];
    __nv_bfloat16 hi = __float2bfloat16(v);
    __nv_bfloat16 lo = __float2bfloat16(v - __bfloat162float(hi));
    size_t base = (size_t)m * (3 * K);
    out[base + k]         = hi;
    out[base + K + k]     = hi;
    out[base + 2 * K + k] = lo;
}

// ---------------------------------------------------------------------------
// Transpose + split-convert weights: W[K,N] fp32 -> Bhat[N,3K] bf16 = [hi|lo|hi]
// ---------------------------------------------------------------------------
__global__ void convert_split_wT(const float* __restrict__ W,
                                 __nv_bfloat16* __restrict__ out, int K, int N)
{
    __shared__ float t[32][33];
    const int tx = threadIdx.x, ty = threadIdx.y;   // block (32, 8)
    const int n0 = blockIdx.x * 32, k0 = blockIdx.y * 32;
    #pragma unroll
    for (int j = 0; j < 4; j++)
        t[ty + j * 8][tx] = W[(size_t)(k0 + ty + j * 8) * N + n0 + tx];
    __syncthreads();
    #pragma unroll
    for (int j = 0; j < 4; j++) {
        const int nn = ty + j * 8;
        float v = t[tx][nn];
        __nv_bfloat16 hi = __float2bfloat16(v);
        __nv_bfloat16 lo = __float2bfloat16(v - __bfloat162float(hi));
        size_t base = (size_t)(n0 + nn) * (3 * K) + k0 + tx;
        out[base]         = hi;
        out[base + K]     = lo;
        out[base + 2 * K] = hi;
    }
}

// ---------------------------------------------------------------------------
// mma.sync bf16 GEMM (unchanged from R3 — verified)
// ---------------------------------------------------------------------------
#define GBK   32
#define NSTG  (K3 / GBK)          // 96
#define APAD  40
#define TILE_ELEMS (128 * APAD)

__global__ __launch_bounds__(256) void gemm_mma(
    const __nv_bfloat16* __restrict__ A,
    const __nv_bfloat16* __restrict__ B,
    const float* __restrict__ bias,
    float* __restrict__ C, int M, int N)
{
    __shared__ __align__(16) __nv_bfloat16 smA[2][TILE_ELEMS];
    __shared__ __align__(16) __nv_bfloat16 smB[2][TILE_ELEMS];

    const int tid  = threadIdx.x;
    const int wid  = tid >> 5;
    const int lane = tid & 31;
    const int wm   = wid & 3;
    const int wn   = wid >> 2;
    const int row0 = blockIdx.y * 128;
    const int col0 = blockIdx.x * 128;

    const uint32_t smA_b = smem_u32(smA);
    const uint32_t smB_b = smem_u32(smB);
    const uint32_t BUFB  = TILE_ELEMS * 2;

    const __nv_bfloat16* Arow = A + (size_t)row0 * K3;
    const __nv_bfloat16* Brow = B + (size_t)col0 * K3;

    auto load_stage = [&](int s, int buf) {
        const int k0 = s * GBK;
        #pragma unroll
        for (int i = 0; i < 2; i++) {
            const int idx = i * 256 + tid;
            const int r   = idx >> 2;
            const int c   = idx & 3;
            const uint32_t so = (uint32_t)(r * 80 + c * 16);
            CP_ASYNC16(smA_b + buf * BUFB + so, Arow + (size_t)r * K3 + k0 + c * 8);
            CP_ASYNC16(smB_b + buf * BUFB + so, Brow + (size_t)r * K3 + k0 + c * 8);
        }
    };

    float acc[2][8][4];
    #pragma unroll
    for (int i = 0; i < 2; i++)
        #pragma unroll
        for (int j = 0; j < 8; j++)
            #pragma unroll
            for (int k = 0; k < 4; k++) acc[i][j][k] = 0.f;

    const int lrow = lane & 15;
    const int lcol = (lane >> 4) << 4;

    load_stage(0, 0);
    CP_COMMIT();

    for (int s = 0; s < NSTG; s++) {
        const int buf = s & 1;
        if (s + 1 < NSTG) {
            load_stage(s + 1, (s + 1) & 1);
            CP_COMMIT();
            CP_WAIT(1);
        } else {
            CP_WAIT(0);
        }
        __syncthreads();

        const uint32_t aB = smA_b + buf * BUFB;
        const uint32_t bB = smB_b + buf * BUFB;

        #pragma unroll
        for (int ks = 0; ks < 2; ks++) {
            uint32_t a[2][4], bf[4][4];
            #pragma unroll
            for (int fm = 0; fm < 2; fm++) {
                const uint32_t ad = aB +
                    (uint32_t)((wm * 32 + fm * 16 + lrow) * 80 + ks * 32) + lcol;
                LDSM_X4(a[fm][0], a[fm][1], a[fm][2], a[fm][3], ad);
            }
            #pragma unroll
            for (int g = 0; g < 4; g++) {
                const uint32_t bd = bB +
                    (uint32_t)((wn * 64 + g * 16 + lrow) * 80 + ks * 32) + lcol;
                LDSM_X4(bf[g][0], bf[g][1], bf[g][2], bf[g][3], bd);
            }
            #pragma unroll
            for (int fm = 0; fm < 2; fm++)
                #pragma unroll
                for (int fn = 0; fn < 8; fn++) {
                    const int g = fn >> 1, h = fn & 1;
                    MMA_BF16(acc[fm][fn][0], acc[fm][fn][1],
                             acc[fm][fn][2], acc[fm][fn][3],
                             a[fm][0], a[fm][1], a[fm][2], a[fm][3],
                             bf[g][h], bf[g][2 + h]);
                }
        }
        __syncthreads();
    }

    const int erow = lane >> 2;
    const int ecol = (lane & 3) << 1;
    #pragma unroll
    for (int fm = 0; fm < 2; fm++) {
        const int r0g = row0 + wm * 32 + fm * 16 + erow;
        #pragma unroll
        for (int fn = 0; fn < 8; fn++) {
            const int cg = col0 + wn * 64 + fn * 8 + ecol;
            const float b0 = bias[cg], b1 = bias[cg + 1];
            float2 v0 = make_float2(acc[fm][fn][0] + b0, acc[fm][fn][1] + b1);
            float2 v1 = make_float2(acc[fm][fn][2] + b0, acc[fm][fn][3] + b1);
            *reinterpret_cast<float2*>(&C[(size_t)r0g * N + cg]) = v0;
            *reinterpret_cast<float2*>(&C[(size_t)(r0g + 8) * N + cg]) = v1;
        }
    }
}

// ---------------------------------------------------------------------------
// Tensor-core causal flash attention with split-bf16 (3-term) precision.
// 128 threads (4 warps), 64 q-rows/CTA; warp w owns rows 16w..16w+15.
// Smem: Qhat[64][136]=[hiQ|loQ], Khat[64][136]=[hiK|loK],
//       Vt[64][136]=[hiV|loV] (transposed via fp32 staging [64][65]),
// All operands feed the SAME ldmatrix/mma pattern verified in gemm_mma.
// ---------------------------------------------------------------------------
#define ASTR  136              // bf16 elements per smem row
#define ASTRB 272              // bytes per row
#define AT_QS  0
#define AT_KS  (64 * ASTRB)                 // 17408
#define AT_VT  (2 * 64 * ASTRB)             // 34816
#define AT_VST (3 * 64 * ASTRB)             // 52224 (fp32 stage [64][65])
#define ATTN_SMEM (AT_VST + 64 * 65 * 4)    // 68864 bytes

__global__ __launch_bounds__(128) void attn_mma(
    const float* __restrict__ qkv, float* __restrict__ out)
{
    extern __shared__ __align__(16) unsigned char smraw[];
    __nv_bfloat16* Qs  = reinterpret_cast<__nv_bfloat16*>(smraw + AT_QS);
    __nv_bfloat16* Ks  = reinterpret_cast<__nv_bfloat16*>(smraw + AT_KS);
    __nv_bfloat16* Vts = reinterpret_cast<__nv_bfloat16*>(smraw + AT_VT);
    float*         Vst = reinterpret_cast<float*>(smraw + AT_VST);

    const int qt   = (gridDim.x - 1) - blockIdx.x;   // heavy tiles first
    const int h    = blockIdx.y;
    const int b    = blockIdx.z;
    const int tid  = threadIdx.x;
    const int wid  = tid >> 5;
    const int lane = tid & 31;
    const int q0   = qt * 64;

    const size_t base = (size_t)b * TSEQ * THREEC;
    const int qoff = h * HD;
    const int koff = CDIM + h * HD;
    const int voff = 2 * CDIM + h * HD;

    const uint32_t QsB  = smem_u32(Qs);
    const uint32_t KsB  = smem_u32(Ks);
    const uint32_t VtsB = smem_u32(Vts);

    // ---- Load Q tile, split hi/lo into Qs ----
    #pragma unroll
    for (int e = 0; e < 32; e++) {
        const int lin = e * 128 + tid;
        const int r = lin >> 6, d = lin & 63;
        const float v = qkv[base + (size_t)(q0 + r) * THREEC + qoff + d];
        const __nv_bfloat16 hi = __float2bfloat16(v);
        Qs[r * ASTR + d]      = hi;
        Qs[r * ASTR + 64 + d] = __float2bfloat16(v - __bfloat162float(hi));
    }
    __syncthreads();

    // ---- Q fragments in registers (hi: ks0..3 from cols 0..63; lo: 64..127) ----
    const int lrow  = lane & 15;
    const int lcolb = (lane >> 4) << 4;
    uint32_t ahi[4][4], alo[4][4];
    #pragma unroll
    for (int ks = 0; ks < 4; ks++) {
        const uint32_t ad = QsB + (uint32_t)((16 * wid + lrow) * ASTRB + ks * 32) + lcolb;
        LDSM_X4(ahi[ks][0], ahi[ks][1], ahi[ks][2], ahi[ks][3], ad);
        LDSM_X4(alo[ks][0], alo[ks][1], alo[ks][2], alo[ks][3], ad + 128);
    }

    float oacc[8][4];
    #pragma unroll
    for (int t = 0; t < 8; t++)
        #pragma unroll
        for (int j = 0; j < 4; j++) oacc[t][j] = 0.f;
    float m0r = -1.0e30f, m1r = -1.0e30f, l0 = 0.f, l1 = 0.f;

    const int   rl0   = 16 * wid + (lane >> 2);   // local q-row of c0/c1
    const int   rl1   = rl0 + 8;
    const float scale = 0.125f;

    for (int kt = 0; kt <= qt; kt++) {
        const int k0 = kt * 64;
        __syncthreads();   // prev iter done with Ks/Vts/Vst

        // ---- Load K (split hi/lo) + V (fp32 stage) ----
        #pragma unroll
        for (int e = 0; e < 32; e++) {
            const int lin = e * 128 + tid;
            const int r = lin >> 6, d = lin & 63;
            const size_t rowb = base + (size_t)(k0 + r) * THREEC;
            const float kv = qkv[rowb + koff + d];
            const __nv_bfloat16 khi = __float2bfloat16(kv);
            Ks[r * ASTR + d]      = khi;
            Ks[r * ASTR + 64 + d] = __float2bfloat16(kv - __bfloat162float(khi));
            Vst[r * 65 + d] = qkv[rowb + voff + d];
        }
        __syncthreads();

        // ---- S = Qhat · Khat^T  (3 split terms x 4 k16-steps x 8 n-tiles) ----
        float sf[8][4];
        #pragma unroll
        for (int t = 0; t < 8; t++)
            #pragma unroll
            for (int j = 0; j < 4; j++) sf[t][j] = 0.f;

        #pragma unroll
        for (int term = 0; term < 3; term++) {
            const uint32_t cb = (term == 1) ? 128u : 0u;   // loK at +128B
            #pragma unroll
            for (int ks = 0; ks < 4; ks++) {
                const uint32_t* af = (term == 2) ? alo[ks] : ahi[ks];
                uint32_t bq[4][4];
                #pragma unroll
                for (int g = 0; g < 4; g++) {
                    const uint32_t bd = KsB +
                        (uint32_t)((g * 16 + lrow) * ASTRB + ks * 32) + cb + lcolb;
                    LDSM_X4(bq[g][0], bq[g][1], bq[g][2], bq[g][3], bd);
                }
                #pragma unroll
                for (int g = 0; g < 4; g++)
                    #pragma unroll
                    for (int hh = 0; hh < 2; hh++) {
                        const int t = 2 * g + hh;
                        MMA_BF16(sf[t][0], sf[t][1], sf[t][2], sf[t][3],
                                 af[0], af[1], af[2], af[3],
                                 bq[g][hh], bq[g][2 + hh]);
                    }
            }
        }

        // ---- Scale + causal mask ----
        if (kt == qt) {
            #pragma unroll
            for (int t = 0; t < 8; t++) {
                const int c = t * 8 + 2 * (lane & 3);
                sf[t][0] = (c     <= rl0) ? sf[t][0] * scale : -1.0e30f;
                sf[t][1] = (c + 1 <= rl0) ? sf[t][1] * scale : -1.0e30f;
                sf[t][2] = (c     <= rl1) ? sf[t][2] * scale : -1.0e30f;
                sf[t][3] = (c + 1 <= rl1) ? sf[t][3] * scale : -1.0e30f;
            }
        } else {
            #pragma unroll
            for (int t = 0; t < 8; t++)
                #pragma unroll
                for (int j = 0; j < 4; j++) sf[t][j] *= scale;
        }

        // ---- Online softmax ----
        float rm0 = -1.0e30f, rm1 = -1.0e30f;
        #pragma unroll
        for (int t = 0; t < 8; t++) {
            rm0 = fmaxf(rm0, fmaxf(sf[t][0], sf[t][1]));
            rm1 = fmaxf(rm1, fmaxf(sf[t][2], sf[t][3]));
        }
        rm0 = fmaxf(rm0, __shfl_xor_sync(0xffffffffu, rm0, 1));
        rm0 = fmaxf(rm0, __shfl_xor_sync(0xffffffffu, rm0, 2));
        rm1 = fmaxf(rm1, __shfl_xor_sync(0xffffffffu, rm1, 1));
        rm1 = fmaxf(rm1, __shfl_xor_sync(0xffffffffu, rm1, 2));
        const float mn0 = fmaxf(m0r, rm0);
        const float mn1 = fmaxf(m1r, rm1);

        float sum0 = 0.f, sum1 = 0.f;
        #pragma unroll
        for (int t = 0; t < 8; t++) {
            sf[t][0] = __expf(sf[t][0] - mn0);
            sf[t][1] = __expf(sf[t][1] - mn0);
            sf[t][2] = __expf(sf[t][2] - mn1);
            sf[t][3] = __expf(sf[t][3] - mn1);
            sum0 += sf[t][0] + sf[t][1];
            sum1 += sf[t][2] + sf[t][3];
        }
        sum0 += __shfl_xor_sync(0xffffffffu, sum0, 1);
        sum0 += __shfl_xor_sync(0xffffffffu, sum0, 2);
        sum1 += __shfl_xor_sync(0xffffffffu, sum1, 1);
        sum1 += __shfl_xor_sync(0xffffffffu, sum1, 2);

        const float al0 = __expf(m0r - mn0);
        const float al1 = __expf(m1r - mn1);
        l0 = l0 * al0 + sum0;  m0r = mn0;
        l1 = l1 * al1 + sum1;  m1r = mn1;
        #pragma unroll
        for (int t = 0; t < 8; t++) {
            oacc[t][0] *= al0; oacc[t][1] *= al0;
            oacc[t][2] *= al1; oacc[t][3] *= al1;
        }

        // ---- P fragments (A-operand) direct from S fragments, hi/lo split ----
        uint32_t phi[4][4], plo[4][4];
        #pragma unroll
        for (int ks = 0; ks < 4; ks++) {
            const float* e0 = sf[2 * ks];       // cols 16ks..16ks+7
            const float* e1 = sf[2 * ks + 1];   // cols 16ks+8..+15
            #pragma unroll
            for (int q = 0; q < 2; q++) {       // q=0: tile e0 -> a0,a1 ; q=1: e1 -> a2,a3
                const float* e = q ? e1 : e0;
                float hx0 = __bfloat162float(__float2bfloat16(e[0]));
                float hx1 = __bfloat162float(__float2bfloat16(e[1]));
                float hx2 = __bfloat162float(__float2bfloat16(e[2]));
                float hx3 = __bfloat162float(__float2bfloat16(e[3]));
                phi[ks][2 * q]     = pack_bf16(e[0], e[1]);
                phi[ks][2 * q + 1] = pack_bf16(e[2], e[3]);
                plo[ks][2 * q]     = pack_bf16(e[0] - hx0, e[1] - hx1);
                plo[ks][2 * q + 1] = pack_bf16(e[2] - hx2, e[3] - hx3);
            }
        }

        // ---- Transpose V: Vst[k][d] -> Vts[d][k](hi), [64+k](lo) ----
        #pragma unroll
        for (int e = 0; e < 32; e++) {
            const int lin = e * 128 + tid;
            const int d = lin >> 6, k = lin & 63;
            const float v = Vst[k * 65 + d];       // banks (k+d)%32: conflict-free
            const __nv_bfloat16 vhi = __float2bfloat16(v);
            Vts[d * ASTR + k]      = vhi;
            Vts[d * ASTR + 64 + k] = __float2bfloat16(v - __bfloat162float(vhi));
        }
        __syncthreads();

        // ---- O += Phat · Vthat^T  (3 terms x 4 ks x 8 d-tiles) ----
        #pragma unroll
        for (int term = 0; term < 3; term++) {
            const uint32_t cb = (term == 1) ? 128u : 0u;   // loV at +128B
            #pragma unroll
            for (int ks = 0; ks < 4; ks++) {
                const uint32_t* pf = (term == 2) ? plo[ks] : phi[ks];
                uint32_t bq[4][4];
                #pragma unroll
                for (int g = 0; g < 4; g++) {
                    const uint32_t bd = VtsB +
                        (uint32_t)((g * 16 + lrow) * ASTRB + ks * 32) + cb + lcolb;
                    LDSM_X4(bq[g][0], bq[g][1], bq[g][2], bq[g][3], bd);
                }
                #pragma unroll
                for (int g = 0; g < 4; g++)
                    #pragma unroll
                    for (int hh = 0; hh < 2; hh++) {
                        const int t = 2 * g + hh;
                        MMA_BF16(oacc[t][0], oacc[t][1], oacc[t][2], oacc[t][3],
                                 pf[0], pf[1], pf[2], pf[3],
                                 bq[g][hh], bq[g][2 + hh]);
                    }
            }
        }
    }

    // ---- Epilogue ----
    const float inv0 = 1.0f / l0;
    const float inv1 = 1.0f / l1;
    const int r0g = q0 + rl0;
    const int r1g = q0 + rl1;
    const size_t ob0 = ((size_t)b * TSEQ + r0g) * CDIM + h * HD;
    const size_t ob1 = ((size_t)b * TSEQ + r1g) * CDIM + h * HD;
    #pragma unroll
    for (int t = 0; t < 8; t++) {
        const int cg = t * 8 + 2 * (lane & 3);
        *reinterpret_cast<float2*>(&out[ob0 + cg]) =
            make_float2(oacc[t][0] * inv0, oacc[t][1] * inv0);
        *reinterpret_cast<float2*>(&out[ob1 + cg]) =
            make_float2(oacc[t][2] * inv1, oacc[t][3] * inv1);
    }
}

// ---------------------------------------------------------------------------
// Launch
// ---------------------------------------------------------------------------
extern "C" void kernel_launch(void* const* d_in, const int* in_sizes, int n_in,
                              void* d_out, int out_size)
{
    const float* x     = (const float*)d_in[0];
    const float* Wqkv  = (const float*)d_in[1];
    const float* bqkv  = (const float*)d_in[2];
    const float* Wproj = (const float*)d_in[3];
    const float* bproj = (const float*)d_in[4];
    float* out = (float*)d_out;

    float *qkv, *att;
    __nv_bfloat16 *ahat, *bqkvp, *bprojp;
    cudaGetSymbolAddress((void**)&qkv,    g_qkv);
    cudaGetSymbolAddress((void**)&att,    g_att);
    cudaGetSymbolAddress((void**)&ahat,   g_ahat);
    cudaGetSymbolAddress((void**)&bqkvp,  g_bqkv);
    cudaGetSymbolAddress((void**)&bprojp, g_bproj);

    cudaFuncSetAttribute(attn_mma,
                         cudaFuncAttributeMaxDynamicSharedMemorySize, ATTN_SMEM);

    // Pack weights
    {
        dim3 bb(32, 8);
        convert_split_wT<<<dim3(THREEC / 32, CDIM / 32), bb>>>(Wqkv, bqkvp, CDIM, THREEC);
        convert_split_wT<<<dim3(CDIM / 32, CDIM / 32), bb>>>(Wproj, bprojp, CDIM, CDIM);
    }

    // 1) Pack x and run QKV GEMM
    convert_split_act<<<(MROWS * CDIM + 255) / 256, 256>>>(x, ahat, MROWS * CDIM, CDIM);
    gemm_mma<<<dim3(THREEC / 128, MROWS / 128), 256>>>(ahat, bqkvp, bqkv, qkv, MROWS, THREEC);

    // 2) Causal attention (tensor-core, split-bf16)
    attn_mma<<<dim3(TSEQ / 64, NH, BATCH), 128, ATTN_SMEM>>>(qkv, att);

    // 3) Pack att and run output projection
    convert_split_act<<<(MROWS * CDIM + 255) / 256, 256>>>(att, ahat, MROWS * CDIM, CDIM);
    gemm_mma<<<dim3(CDIM / 128, MROWS / 128), 256>>>(ahat, bprojp, bproj, out, MROWS, CDIM);
}

// round 5
// speedup vs baseline: 2.2125x; 1.0030x over previous
#include <cuda_runtime.h>
#include <cuda_bf16.h>
#include <math.h>
#include <cstdint>

// Problem constants
#define BATCH 2
#define TSEQ  2048
#define CDIM  1024
#define NH    16
#define HD    64
#define THREEC (3*CDIM)
#define MROWS (BATCH*TSEQ)   // 4096
#define K3    (3*CDIM)       // packed split-K = 3072

// ---------------------------------------------------------------------------
// Scratch (__device__ globals; allocation-free rule)
// ---------------------------------------------------------------------------
__device__ float         g_qkv[(size_t)MROWS * THREEC];    // [B*T, 3C] fp32
__device__ __nv_bfloat16 g_ahat[(size_t)MROWS * K3];       // packed activations
__device__ __nv_bfloat16 g_bqkv[(size_t)THREEC * K3];      // packed Wqkv^T
__device__ __nv_bfloat16 g_bproj[(size_t)CDIM * K3];       // packed Wproj^T

// ---------------------------------------------------------------------------
// Helpers (base-ISA only: cp.async / ldmatrix / mma.sync)
// ---------------------------------------------------------------------------
__device__ __forceinline__ uint32_t smem_u32(const void* p) {
    uint32_t a;
    asm("{ .reg .u64 t; cvta.to.shared.u64 t, %1; cvt.u32.u64 %0, t; }"
        : "=r"(a) : "l"(p));
    return a;
}
#define CP_ASYNC16(smaddr, gptr) \
    asm volatile("cp.async.cg.shared.global [%0], [%1], 16;" \
                 :: "r"(smaddr), "l"(gptr))
#define CP_COMMIT() asm volatile("cp.async.commit_group;" ::: "memory")
#define CP_WAIT(n)  asm volatile("cp.async.wait_group %0;" :: "n"(n) : "memory")

#define LDSM_X4(r0, r1, r2, r3, addr) \
    asm volatile("ldmatrix.sync.aligned.m8n8.x4.shared.b16 {%0,%1,%2,%3}, [%4];" \
                 : "=r"(r0), "=r"(r1), "=r"(r2), "=r"(r3) : "r"(addr))

#define MMA_BF16(c0, c1, c2, c3, a0, a1, a2, a3, b0, b1) \
    asm volatile("mma.sync.aligned.m16n8k16.row.col.f32.bf16.bf16.f32 " \
                 "{%0,%1,%2,%3}, {%4,%5,%6,%7}, {%8,%9}, {%0,%1,%2,%3};" \
                 : "+f"(c0), "+f"(c1), "+f"(c2), "+f"(c3) \
                 : "r"(a0), "r"(a1), "r"(a2), "r"(a3), "r"(b0), "r"(b1))

__device__ __forceinline__ uint32_t pack_bf16(float x, float y) {
    __nv_bfloat162 h = __floats2bfloat162_rn(x, y);
    return *reinterpret_cast<uint32_t*>(&h);
}

// ---------------------------------------------------------------------------
// Split-convert activations: A[M,K] fp32 -> Ahat[M,3K] bf16 = [hi | hi | lo]
// ---------------------------------------------------------------------------
__global__ void convert_split_act(const float* __restrict__ in,
                                  __nv_bfloat16* __restrict__ out, int MK, int K)
{
    int idx = blockIdx.x * blockDim.x + threadIdx.x;
    if (idx >= MK) return;
    int m = idx / K, k = idx - m * K;
    float v = in[idx];
    __nv_bfloat16 hi = __float2bfloat16(v);
    __nv_bfloat16 lo = __float2bfloat16(v - __bfloat162float(hi));
    size_t base = (size_t)m * (3 * K);
    out[base + k]         = hi;
    out[base + K + k]     = hi;
    out[base + 2 * K + k] = lo;
}

// ---------------------------------------------------------------------------
// Transpose + split-convert weights: W[K,N] fp32 -> Bhat[N,3K] bf16 = [hi|lo|hi]
// ---------------------------------------------------------------------------
__global__ void convert_split_wT(const float* __restrict__ W,
                                 __nv_bfloat16* __restrict__ out, int K, int N)
{
    __shared__ float t[32][33];
    const int tx = threadIdx.x, ty = threadIdx.y;   // block (32, 8)
    const int n0 = blockIdx.x * 32, k0 = blockIdx.y * 32;
    #pragma unroll
    for (int j = 0; j < 4; j++)
        t[ty + j * 8][tx] = W[(size_t)(k0 + ty + j * 8) * N + n0 + tx];
    __syncthreads();
    #pragma unroll
    for (int j = 0; j < 4; j++) {
        const int nn = ty + j * 8;
        float v = t[tx][nn];
        __nv_bfloat16 hi = __float2bfloat16(v);
        __nv_bfloat16 lo = __float2bfloat16(v - __bfloat162float(hi));
        size_t base = (size_t)(n0 + nn) * (3 * K) + k0 + tx;
        out[base]         = hi;
        out[base + K]     = lo;
        out[base + 2 * K] = hi;
    }
}

// ---------------------------------------------------------------------------
// mma.sync bf16 GEMM with 4-stage cp.async pipeline.
// 128x128 CTA tile, BK=32, 256 threads (8 warps, warp tile 32x64).
// One __syncthreads per stage; always-commit keeps wait_group count uniform.
// ---------------------------------------------------------------------------
#define GBK   32
#define NSTG  (K3 / GBK)            // 96
#define APAD  40                    // elements per smem row (80 bytes)
#define TILE_ELEMS (128 * APAD)     // 5120 per matrix per stage
#define STAGE_BYTES (TILE_ELEMS * 2)  // 10240
#define STAGES 4
#define GEMM_SMEM (2 * STAGES * STAGE_BYTES)   // 81920 bytes

__global__ __launch_bounds__(256) void gemm_mma(
    const __nv_bfloat16* __restrict__ A,
    const __nv_bfloat16* __restrict__ B,
    const float* __restrict__ bias,
    float* __restrict__ C, int M, int N)
{
    extern __shared__ __align__(16) unsigned char gsm[];

    const int tid  = threadIdx.x;
    const int wid  = tid >> 5;
    const int lane = tid & 31;
    const int wm   = wid & 3;
    const int wn   = wid >> 2;
    const int row0 = blockIdx.y * 128;
    const int col0 = blockIdx.x * 128;

    const uint32_t smA_b = smem_u32(gsm);
    const uint32_t smB_b = smA_b + STAGES * STAGE_BYTES;

    const __nv_bfloat16* Arow = A + (size_t)row0 * K3;
    const __nv_bfloat16* Brow = B + (size_t)col0 * K3;

    auto load_stage = [&](int s, int buf) {
        const int k0 = s * GBK;
        const uint32_t ao = smA_b + buf * STAGE_BYTES;
        const uint32_t bo = smB_b + buf * STAGE_BYTES;
        #pragma unroll
        for (int i = 0; i < 2; i++) {
            const int idx = i * 256 + tid;    // 0..511
            const int r   = idx >> 2;
            const int c   = idx & 3;
            const uint32_t so = (uint32_t)(r * 80 + c * 16);
            CP_ASYNC16(ao + so, Arow + (size_t)r * K3 + k0 + c * 8);
            CP_ASYNC16(bo + so, Brow + (size_t)r * K3 + k0 + c * 8);
        }
    };

    float acc[2][8][4];
    #pragma unroll
    for (int i = 0; i < 2; i++)
        #pragma unroll
        for (int j = 0; j < 8; j++)
            #pragma unroll
            for (int k = 0; k < 4; k++) acc[i][j][k] = 0.f;

    const int lrow = lane & 15;
    const int lcol = (lane >> 4) << 4;

    // Prologue: prefetch STAGES-1 stages
    #pragma unroll
    for (int s = 0; s < STAGES - 1; s++) { load_stage(s, s); CP_COMMIT(); }

    for (int s = 0; s < NSTG; s++) {
        CP_WAIT(STAGES - 2);     // stage s now resident (3 groups always pending)
        __syncthreads();         // also: all warps done computing stage s-1

        if (s + STAGES - 1 < NSTG)
            load_stage(s + STAGES - 1, (s + STAGES - 1) % STAGES);
        CP_COMMIT();             // always commit (possibly empty) -> uniform count

        const int buf = s % STAGES;
        const uint32_t aB = smA_b + buf * STAGE_BYTES;
        const uint32_t bB = smB_b + buf * STAGE_BYTES;

        #pragma unroll
        for (int ks = 0; ks < 2; ks++) {
            uint32_t a[2][4], bf[4][4];
            #pragma unroll
            for (int fm = 0; fm < 2; fm++) {
                const uint32_t ad = aB +
                    (uint32_t)((wm * 32 + fm * 16 + lrow) * 80 + ks * 32) + lcol;
                LDSM_X4(a[fm][0], a[fm][1], a[fm][2], a[fm][3], ad);
            }
            #pragma unroll
            for (int g = 0; g < 4; g++) {
                const uint32_t bd = bB +
                    (uint32_t)((wn * 64 + g * 16 + lrow) * 80 + ks * 32) + lcol;
                LDSM_X4(bf[g][0], bf[g][1], bf[g][2], bf[g][3], bd);
            }
            #pragma unroll
            for (int fm = 0; fm < 2; fm++)
                #pragma unroll
                for (int fn = 0; fn < 8; fn++) {
                    const int g = fn >> 1, h = fn & 1;
                    MMA_BF16(acc[fm][fn][0], acc[fm][fn][1],
                             acc[fm][fn][2], acc[fm][fn][3],
                             a[fm][0], a[fm][1], a[fm][2], a[fm][3],
                             bf[g][h], bf[g][2 + h]);
                }
        }
    }

    const int erow = lane >> 2;
    const int ecol = (lane & 3) << 1;
    #pragma unroll
    for (int fm = 0; fm < 2; fm++) {
        const int r0g = row0 + wm * 32 + fm * 16 + erow;
        #pragma unroll
        for (int fn = 0; fn < 8; fn++) {
            const int cg = col0 + wn * 64 + fn * 8 + ecol;
            const float b0 = bias[cg], b1 = bias[cg + 1];
            float2 v0 = make_float2(acc[fm][fn][0] + b0, acc[fm][fn][1] + b1);
            float2 v1 = make_float2(acc[fm][fn][2] + b0, acc[fm][fn][3] + b1);
            *reinterpret_cast<float2*>(&C[(size_t)r0g * N + cg]) = v0;
            *reinterpret_cast<float2*>(&C[(size_t)(r0g + 8) * N + cg]) = v1;
        }
    }
}

// ---------------------------------------------------------------------------
// Tensor-core causal flash attention with split-bf16 (3-term) precision.
// Output written DIRECTLY in packed [hi|hi|lo] layout for the proj GEMM.
// ---------------------------------------------------------------------------
#define ASTR  136              // bf16 elements per smem row
#define ASTRB 272              // bytes per row
#define AT_QS  0
#define AT_KS  (64 * ASTRB)
#define AT_VT  (2 * 64 * ASTRB)
#define AT_VST (3 * 64 * ASTRB)
#define ATTN_SMEM (AT_VST + 64 * 65 * 4)    // 68864 bytes

__global__ __launch_bounds__(128) void attn_mma(
    const float* __restrict__ qkv, __nv_bfloat16* __restrict__ outp)
{
    extern __shared__ __align__(16) unsigned char smraw[];
    __nv_bfloat16* Qs  = reinterpret_cast<__nv_bfloat16*>(smraw + AT_QS);
    __nv_bfloat16* Ks  = reinterpret_cast<__nv_bfloat16*>(smraw + AT_KS);
    __nv_bfloat16* Vts = reinterpret_cast<__nv_bfloat16*>(smraw + AT_VT);
    float*         Vst = reinterpret_cast<float*>(smraw + AT_VST);

    const int qt   = (gridDim.x - 1) - blockIdx.x;
    const int h    = blockIdx.y;
    const int b    = blockIdx.z;
    const int tid  = threadIdx.x;
    const int wid  = tid >> 5;
    const int lane = tid & 31;
    const int q0   = qt * 64;

    const size_t base = (size_t)b * TSEQ * THREEC;
    const int qoff = h * HD;
    const int koff = CDIM + h * HD;
    const int voff = 2 * CDIM + h * HD;

    const uint32_t QsB  = smem_u32(Qs);
    const uint32_t KsB  = smem_u32(Ks);
    const uint32_t VtsB = smem_u32(Vts);

    #pragma unroll
    for (int e = 0; e < 32; e++) {
        const int lin = e * 128 + tid;
        const int r = lin >> 6, d = lin & 63;
        const float v = qkv[base + (size_t)(q0 + r) * THREEC + qoff + d];
        const __nv_bfloat16 hi = __float2bfloat16(v);
        Qs[r * ASTR + d]      = hi;
        Qs[r * ASTR + 64 + d] = __float2bfloat16(v - __bfloat162float(hi));
    }
    __syncthreads();

    const int lrow  = lane & 15;
    const int lcolb = (lane >> 4) << 4;
    uint32_t ahi[4][4], alo[4][4];
    #pragma unroll
    for (int ks = 0; ks < 4; ks++) {
        const uint32_t ad = QsB + (uint32_t)((16 * wid + lrow) * ASTRB + ks * 32) + lcolb;
        LDSM_X4(ahi[ks][0], ahi[ks][1], ahi[ks][2], ahi[ks][3], ad);
        LDSM_X4(alo[ks][0], alo[ks][1], alo[ks][2], alo[ks][3], ad + 128);
    }

    float oacc[8][4];
    #pragma unroll
    for (int t = 0; t < 8; t++)
        #pragma unroll
        for (int j = 0; j < 4; j++) oacc[t][j] = 0.f;
    float m0r = -1.0e30f, m1r = -1.0e30f, l0 = 0.f, l1 = 0.f;

    const int   rl0   = 16 * wid + (lane >> 2);
    const int   rl1   = rl0 + 8;
    const float scale = 0.125f;

    for (int kt = 0; kt <= qt; kt++) {
        const int k0 = kt * 64;
        __syncthreads();

        #pragma unroll
        for (int e = 0; e < 32; e++) {
            const int lin = e * 128 + tid;
            const int r = lin >> 6, d = lin & 63;
            const size_t rowb = base + (size_t)(k0 + r) * THREEC;
            const float kv = qkv[rowb + koff + d];
            const __nv_bfloat16 khi = __float2bfloat16(kv);
            Ks[r * ASTR + d]      = khi;
            Ks[r * ASTR + 64 + d] = __float2bfloat16(kv - __bfloat162float(khi));
            Vst[r * 65 + d] = qkv[rowb + voff + d];
        }
        __syncthreads();

        float sf[8][4];
        #pragma unroll
        for (int t = 0; t < 8; t++)
            #pragma unroll
            for (int j = 0; j < 4; j++) sf[t][j] = 0.f;

        #pragma unroll
        for (int term = 0; term < 3; term++) {
            const uint32_t cb = (term == 1) ? 128u : 0u;
            #pragma unroll
            for (int ks = 0; ks < 4; ks++) {
                const uint32_t* af = (term == 2) ? alo[ks] : ahi[ks];
                uint32_t bq[4][4];
                #pragma unroll
                for (int g = 0; g < 4; g++) {
                    const uint32_t bd = KsB +
                        (uint32_t)((g * 16 + lrow) * ASTRB + ks * 32) + cb + lcolb;
                    LDSM_X4(bq[g][0], bq[g][1], bq[g][2], bq[g][3], bd);
                }
                #pragma unroll
                for (int g = 0; g < 4; g++)
                    #pragma unroll
                    for (int hh = 0; hh < 2; hh++) {
                        const int t = 2 * g + hh;
                        MMA_BF16(sf[t][0], sf[t][1], sf[t][2], sf[t][3],
                                 af[0], af[1], af[2], af[3],
                                 bq[g][hh], bq[g][2 + hh]);
                    }
            }
        }

        if (kt == qt) {
            #pragma unroll
            for (int t = 0; t < 8; t++) {
                const int c = t * 8 + 2 * (lane & 3);
                sf[t][0] = (c     <= rl0) ? sf[t][0] * scale : -1.0e30f;
                sf[t][1] = (c + 1 <= rl0) ? sf[t][1] * scale : -1.0e30f;
                sf[t][2] = (c     <= rl1) ? sf[t][2] * scale : -1.0e30f;
                sf[t][3] = (c + 1 <= rl1) ? sf[t][3] * scale : -1.0e30f;
            }
        } else {
            #pragma unroll
            for (int t = 0; t < 8; t++)
                #pragma unroll
                for (int j = 0; j < 4; j++) sf[t][j] *= scale;
        }

        float rm0 = -1.0e30f, rm1 = -1.0e30f;
        #pragma unroll
        for (int t = 0; t < 8; t++) {
            rm0 = fmaxf(rm0, fmaxf(sf[t][0], sf[t][1]));
            rm1 = fmaxf(rm1, fmaxf(sf[t][2], sf[t][3]));
        }
        rm0 = fmaxf(rm0, __shfl_xor_sync(0xffffffffu, rm0, 1));
        rm0 = fmaxf(rm0, __shfl_xor_sync(0xffffffffu, rm0, 2));
        rm1 = fmaxf(rm1, __shfl_xor_sync(0xffffffffu, rm1, 1));
        rm1 = fmaxf(rm1, __shfl_xor_sync(0xffffffffu, rm1, 2));
        const float mn0 = fmaxf(m0r, rm0);
        const float mn1 = fmaxf(m1r, rm1);

        float sum0 = 0.f, sum1 = 0.f;
        #pragma unroll
        for (int t = 0; t < 8; t++) {
            sf[t][0] = __expf(sf[t][0] - mn0);
            sf[t][1] = __expf(sf[t][1] - mn0);
            sf[t][2] = __expf(sf[t][2] - mn1);
            sf[t][3] = __expf(sf[t][3] - mn1);
            sum0 += sf[t][0] + sf[t][1];
            sum1 += sf[t][2] + sf[t][3];
        }
        sum0 += __shfl_xor_sync(0xffffffffu, sum0, 1);
        sum0 += __shfl_xor_sync(0xffffffffu, sum0, 2);
        sum1 += __shfl_xor_sync(0xffffffffu, sum1, 1);
        sum1 += __shfl_xor_sync(0xffffffffu, sum1, 2);

        const float al0 = __expf(m0r - mn0);
        const float al1 = __expf(m1r - mn1);
        l0 = l0 * al0 + sum0;  m0r = mn0;
        l1 = l1 * al1 + sum1;  m1r = mn1;
        #pragma unroll
        for (int t = 0; t < 8; t++) {
            oacc[t][0] *= al0; oacc[t][1] *= al0;
            oacc[t][2] *= al1; oacc[t][3] *= al1;
        }

        uint32_t phi[4][4], plo[4][4];
        #pragma unroll
        for (int ks = 0; ks < 4; ks++) {
            const float* e0 = sf[2 * ks];
            const float* e1 = sf[2 * ks + 1];
            #pragma unroll
            for (int q = 0; q < 2; q++) {
                const float* e = q ? e1 : e0;
                float hx0 = __bfloat162float(__float2bfloat16(e[0]));
                float hx1 = __bfloat162float(__float2bfloat16(e[1]));
                float hx2 = __bfloat162float(__float2bfloat16(e[2]));
                float hx3 = __bfloat162float(__float2bfloat16(e[3]));
                phi[ks][2 * q]     = pack_bf16(e[0], e[1]);
                phi[ks][2 * q + 1] = pack_bf16(e[2], e[3]);
                plo[ks][2 * q]     = pack_bf16(e[0] - hx0, e[1] - hx1);
                plo[ks][2 * q + 1] = pack_bf16(e[2] - hx2, e[3] - hx3);
            }
        }

        #pragma unroll
        for (int e = 0; e < 32; e++) {
            const int lin = e * 128 + tid;
            const int d = lin >> 6, k = lin & 63;
            const float v = Vst[k * 65 + d];
            const __nv_bfloat16 vhi = __float2bfloat16(v);
            Vts[d * ASTR + k]      = vhi;
            Vts[d * ASTR + 64 + k] = __float2bfloat16(v - __bfloat162float(vhi));
        }
        __syncthreads();

        #pragma unroll
        for (int term = 0; term < 3; term++) {
            const uint32_t cb = (term == 1) ? 128u : 0u;
            #pragma unroll
            for (int ks = 0; ks < 4; ks++) {
                const uint32_t* pf = (term == 2) ? plo[ks] : phi[ks];
                uint32_t bq[4][4];
                #pragma unroll
                for (int g = 0; g < 4; g++) {
                    const uint32_t bd = VtsB +
                        (uint32_t)((g * 16 + lrow) * ASTRB + ks * 32) + cb + lcolb;
                    LDSM_X4(bq[g][0], bq[g][1], bq[g][2], bq[g][3], bd);
                }
                #pragma unroll
                for (int g = 0; g < 4; g++)
                    #pragma unroll
                    for (int hh = 0; hh < 2; hh++) {
                        const int t = 2 * g + hh;
                        MMA_BF16(oacc[t][0], oacc[t][1], oacc[t][2], oacc[t][3],
                                 pf[0], pf[1], pf[2], pf[3],
                                 bq[g][hh], bq[g][2 + hh]);
                    }
            }
        }
    }

    // ---- Epilogue: write packed [hi|hi|lo] directly for the proj GEMM ----
    const float inv0 = 1.0f / l0;
    const float inv1 = 1.0f / l1;
    const int r0g = q0 + rl0;
    const int r1g = q0 + rl1;
    const size_t pb0 = ((size_t)b * TSEQ + r0g) * K3 + h * HD;
    const size_t pb1 = ((size_t)b * TSEQ + r1g) * K3 + h * HD;
    #pragma unroll
    for (int t = 0; t < 8; t++) {
        const int cg = t * 8 + 2 * (lane & 3);
        const float v00 = oacc[t][0] * inv0, v01 = oacc[t][1] * inv0;
        const float v10 = oacc[t][2] * inv1, v11 = oacc[t][3] * inv1;
        const uint32_t h0 = pack_bf16(v00, v01);
        const uint32_t h1 = pack_bf16(v10, v11);
        __nv_bfloat162 h0b = *reinterpret_cast<const __nv_bfloat162*>(&h0);
        __nv_bfloat162 h1b = *reinterpret_cast<const __nv_bfloat162*>(&h1);
        const uint32_t l0p = pack_bf16(v00 - __bfloat162float(h0b.x),
                                       v01 - __bfloat162float(h0b.y));
        const uint32_t l1p = pack_bf16(v10 - __bfloat162float(h1b.x),
                                       v11 - __bfloat162float(h1b.y));
        *reinterpret_cast<uint32_t*>(&outp[pb0 + cg])            = h0;
        *reinterpret_cast<uint32_t*>(&outp[pb0 + CDIM + cg])     = h0;
        *reinterpret_cast<uint32_t*>(&outp[pb0 + 2 * CDIM + cg]) = l0p;
        *reinterpret_cast<uint32_t*>(&outp[pb1 + cg])            = h1;
        *reinterpret_cast<uint32_t*>(&outp[pb1 + CDIM + cg])     = h1;
        *reinterpret_cast<uint32_t*>(&outp[pb1 + 2 * CDIM + cg]) = l1p;
    }
}

// ---------------------------------------------------------------------------
// Launch
// ---------------------------------------------------------------------------
extern "C" void kernel_launch(void* const* d_in, const int* in_sizes, int n_in,
                              void* d_out, int out_size)
{
    const float* x     = (const float*)d_in[0];
    const float* Wqkv  = (const float*)d_in[1];
    const float* bqkv  = (const float*)d_in[2];
    const float* Wproj = (const float*)d_in[3];
    const float* bproj = (const float*)d_in[4];
    float* out = (float*)d_out;

    float *qkv;
    __nv_bfloat16 *ahat, *bqkvp, *bprojp;
    cudaGetSymbolAddress((void**)&qkv,    g_qkv);
    cudaGetSymbolAddress((void**)&ahat,   g_ahat);
    cudaGetSymbolAddress((void**)&bqkvp,  g_bqkv);
    cudaGetSymbolAddress((void**)&bprojp, g_bproj);

    cudaFuncSetAttribute(attn_mma,
                         cudaFuncAttributeMaxDynamicSharedMemorySize, ATTN_SMEM);
    cudaFuncSetAttribute(gemm_mma,
                         cudaFuncAttributeMaxDynamicSharedMemorySize, GEMM_SMEM);

    // Pack weights
    {
        dim3 bb(32, 8);
        convert_split_wT<<<dim3(THREEC / 32, CDIM / 32), bb>>>(Wqkv, bqkvp, CDIM, THREEC);
        convert_split_wT<<<dim3(CDIM / 32, CDIM / 32), bb>>>(Wproj, bprojp, CDIM, CDIM);
    }

    // 1) Pack x and run QKV GEMM
    convert_split_act<<<(MROWS * CDIM + 255) / 256, 256>>>(x, ahat, MROWS * CDIM, CDIM);
    gemm_mma<<<dim3(THREEC / 128, MROWS / 128), 256, GEMM_SMEM>>>(
        ahat, bqkvp, bqkv, qkv, MROWS, THREEC);

    // 2) Causal attention (tensor-core, split-bf16) -> packed proj input
    attn_mma<<<dim3(TSEQ / 64, NH, BATCH), 128, ATTN_SMEM>>>(qkv, ahat);

    // 3) Output projection (reads packed attention output directly)
    gemm_mma<<<dim3(CDIM / 128, MROWS / 128), 256, GEMM_SMEM>>>(
        ahat, bprojp, bproj, out, MROWS, CDIM);
}

// round 6
// speedup vs baseline: 2.4280x; 1.0974x over previous
#include <cuda_runtime.h>
#include <cuda_bf16.h>
#include <math.h>
#include <cstdint>

// Problem constants
#define BATCH 2
#define TSEQ  2048
#define CDIM  1024
#define NH    16
#define HD    64
#define THREEC (3*CDIM)
#define MROWS (BATCH*TSEQ)   // 4096
#define K2    (2*CDIM)       // [hi|lo] packed K = 2048

// ---------------------------------------------------------------------------
// Scratch (__device__ globals; allocation-free rule)
// ---------------------------------------------------------------------------
__device__ float         g_qkv[(size_t)MROWS * THREEC];    // [B*T, 3C] fp32
__device__ __nv_bfloat16 g_ahat[(size_t)MROWS * K2];       // packed activations
__device__ __nv_bfloat16 g_bqkv[(size_t)THREEC * K2];      // packed Wqkv^T
__device__ __nv_bfloat16 g_bproj[(size_t)CDIM * K2];       // packed Wproj^T

// ---------------------------------------------------------------------------
// Helpers (base-ISA only: cp.async / ldmatrix / mma.sync)
// ---------------------------------------------------------------------------
__device__ __forceinline__ uint32_t smem_u32(const void* p) {
    uint32_t a;
    asm("{ .reg .u64 t; cvta.to.shared.u64 t, %1; cvt.u32.u64 %0, t; }"
        : "=r"(a) : "l"(p));
    return a;
}
#define CP_ASYNC16(smaddr, gptr) \
    asm volatile("cp.async.cg.shared.global [%0], [%1], 16;" \
                 :: "r"(smaddr), "l"(gptr))
#define CP_COMMIT() asm volatile("cp.async.commit_group;" ::: "memory")
#define CP_WAIT(n)  asm volatile("cp.async.wait_group %0;" :: "n"(n) : "memory")

#define LDSM_X4(r0, r1, r2, r3, addr) \
    asm volatile("ldmatrix.sync.aligned.m8n8.x4.shared.b16 {%0,%1,%2,%3}, [%4];" \
                 : "=r"(r0), "=r"(r1), "=r"(r2), "=r"(r3) : "r"(addr))

#define MMA_BF16(c0, c1, c2, c3, a0, a1, a2, a3, b0, b1) \
    asm volatile("mma.sync.aligned.m16n8k16.row.col.f32.bf16.bf16.f32 " \
                 "{%0,%1,%2,%3}, {%4,%5,%6,%7}, {%8,%9}, {%0,%1,%2,%3};" \
                 : "+f"(c0), "+f"(c1), "+f"(c2), "+f"(c3) \
                 : "r"(a0), "r"(a1), "r"(a2), "r"(a3), "r"(b0), "r"(b1))

__device__ __forceinline__ uint32_t pack_bf16(float x, float y) {
    __nv_bfloat162 h = __floats2bfloat162_rn(x, y);
    return *reinterpret_cast<uint32_t*>(&h);
}

// ---------------------------------------------------------------------------
// Split-convert activations: A[M,K] fp32 -> Ahat[M,2K] bf16 = [hi | lo]
// ---------------------------------------------------------------------------
__global__ void convert_split_act(const float* __restrict__ in,
                                  __nv_bfloat16* __restrict__ out, int MK, int K)
{
    int idx = blockIdx.x * blockDim.x + threadIdx.x;
    if (idx >= MK) return;
    int m = idx / K, k = idx - m * K;
    float v = in[idx];
    __nv_bfloat16 hi = __float2bfloat16(v);
    __nv_bfloat16 lo = __float2bfloat16(v - __bfloat162float(hi));
    size_t base = (size_t)m * (2 * K);
    out[base + k]     = hi;
    out[base + K + k] = lo;
}

// ---------------------------------------------------------------------------
// Transpose + split-convert weights: W[K,N] fp32 -> Bhat[N,2K] bf16 = [hi|lo]
// ---------------------------------------------------------------------------
__global__ void convert_split_wT(const float* __restrict__ W,
                                 __nv_bfloat16* __restrict__ out, int K, int N)
{
    __shared__ float t[32][33];
    const int tx = threadIdx.x, ty = threadIdx.y;   // block (32, 8)
    const int n0 = blockIdx.x * 32, k0 = blockIdx.y * 32;
    #pragma unroll
    for (int j = 0; j < 4; j++)
        t[ty + j * 8][tx] = W[(size_t)(k0 + ty + j * 8) * N + n0 + tx];
    __syncthreads();
    #pragma unroll
    for (int j = 0; j < 4; j++) {
        const int nn = ty + j * 8;
        float v = t[tx][nn];
        __nv_bfloat16 hi = __float2bfloat16(v);
        __nv_bfloat16 lo = __float2bfloat16(v - __bfloat162float(hi));
        size_t base = (size_t)(n0 + nn) * (2 * K) + k0 + tx;
        out[base]     = hi;
        out[base + K] = lo;
    }
}

// ---------------------------------------------------------------------------
// mma.sync bf16 GEMM, [hi|lo] operands + register-level 3-term split.
// 128x128 CTA tile, 32 original-K per stage (64 packed cols), 256 threads,
// 3-stage cp.async ring, 144B smem rows (conflict-free for ldmatrix).
// S += Ahi.Bhi + Ahi.Blo + Alo.Bhi
// ---------------------------------------------------------------------------
#define GBK   32                      // original K cols per stage
#define NSTG  (CDIM / GBK)            // 32
#define ROWB  144                     // bytes per smem row (64 packed cols + pad)
#define STAGE_BYTES (128 * ROWB)      // 18432 per matrix per stage
#define STAGES 3
#define GEMM_SMEM (2 * STAGES * STAGE_BYTES)   // 110592 bytes

__global__ __launch_bounds__(256) void gemm_mma(
    const __nv_bfloat16* __restrict__ A,   // [M, K2]
    const __nv_bfloat16* __restrict__ B,   // [N, K2]
    const float* __restrict__ bias,
    float* __restrict__ C, int M, int N)
{
    extern __shared__ __align__(16) unsigned char gsm[];

    const int tid  = threadIdx.x;
    const int wid  = tid >> 5;
    const int lane = tid & 31;
    const int wm   = wid & 3;
    const int wn   = wid >> 2;
    const int row0 = blockIdx.y * 128;
    const int col0 = blockIdx.x * 128;

    const uint32_t smA_b = smem_u32(gsm);
    const uint32_t smB_b = smA_b + STAGES * STAGE_BYTES;

    const __nv_bfloat16* Arow = A + (size_t)row0 * K2;
    const __nv_bfloat16* Brow = B + (size_t)col0 * K2;

    // Per stage: hi cols k0..k0+31 at smem bytes [0,64), lo at [64,128).
    auto load_stage = [&](int s, int buf) {
        const int k0 = s * GBK;
        const uint32_t ao = smA_b + buf * STAGE_BYTES;
        const uint32_t bo = smB_b + buf * STAGE_BYTES;
        #pragma unroll
        for (int i = 0; i < 4; i++) {           // 1024 chunks / 256 threads
            const int idx = i * 256 + tid;
            const int r   = idx >> 3;           // 0..127
            const int c   = idx & 7;            // 0..3 hi, 4..7 lo
            const int cc  = c & 3;
            const int gofs = (c < 4) ? (k0 + cc * 8) : (CDIM + k0 + cc * 8);
            const uint32_t so = (uint32_t)(r * ROWB + cc * 16 + ((c < 4) ? 0 : 64));
            CP_ASYNC16(ao + so, Arow + (size_t)r * K2 + gofs);
            CP_ASYNC16(bo + so, Brow + (size_t)r * K2 + gofs);
        }
    };

    float acc[2][8][4];
    #pragma unroll
    for (int i = 0; i < 2; i++)
        #pragma unroll
        for (int j = 0; j < 8; j++)
            #pragma unroll
            for (int k = 0; k < 4; k++) acc[i][j][k] = 0.f;

    const int lrow = lane & 15;
    const int lcol = (lane >> 4) << 4;

    #pragma unroll
    for (int s = 0; s < STAGES - 1; s++) { load_stage(s, s); CP_COMMIT(); }

    for (int s = 0; s < NSTG; s++) {
        CP_WAIT(STAGES - 2);
        __syncthreads();

        if (s + STAGES - 1 < NSTG)
            load_stage(s + STAGES - 1, (s + STAGES - 1) % STAGES);
        CP_COMMIT();

        const int buf = s % STAGES;
        const uint32_t aB = smA_b + buf * STAGE_BYTES;
        const uint32_t bB = smB_b + buf * STAGE_BYTES;

        #pragma unroll
        for (int ks = 0; ks < 2; ks++) {
            uint32_t ahi[2][4], alo[2][4], bhi[4][4], blo[4][4];
            #pragma unroll
            for (int fm = 0; fm < 2; fm++) {
                const uint32_t ad = aB +
                    (uint32_t)((wm * 32 + fm * 16 + lrow) * ROWB + ks * 32) + lcol;
                LDSM_X4(ahi[fm][0], ahi[fm][1], ahi[fm][2], ahi[fm][3], ad);
                LDSM_X4(alo[fm][0], alo[fm][1], alo[fm][2], alo[fm][3], ad + 64);
            }
            #pragma unroll
            for (int g = 0; g < 4; g++) {
                const uint32_t bd = bB +
                    (uint32_t)((wn * 64 + g * 16 + lrow) * ROWB + ks * 32) + lcol;
                LDSM_X4(bhi[g][0], bhi[g][1], bhi[g][2], bhi[g][3], bd);
                LDSM_X4(blo[g][0], blo[g][1], blo[g][2], blo[g][3], bd + 64);
            }
            #pragma unroll
            for (int fm = 0; fm < 2; fm++)
                #pragma unroll
                for (int fn = 0; fn < 8; fn++) {
                    const int g = fn >> 1, h = fn & 1;
                    MMA_BF16(acc[fm][fn][0], acc[fm][fn][1],
                             acc[fm][fn][2], acc[fm][fn][3],
                             ahi[fm][0], ahi[fm][1], ahi[fm][2], ahi[fm][3],
                             bhi[g][h], bhi[g][2 + h]);
                    MMA_BF16(acc[fm][fn][0], acc[fm][fn][1],
                             acc[fm][fn][2], acc[fm][fn][3],
                             ahi[fm][0], ahi[fm][1], ahi[fm][2], ahi[fm][3],
                             blo[g][h], blo[g][2 + h]);
                    MMA_BF16(acc[fm][fn][0], acc[fm][fn][1],
                             acc[fm][fn][2], acc[fm][fn][3],
                             alo[fm][0], alo[fm][1], alo[fm][2], alo[fm][3],
                             bhi[g][h], bhi[g][2 + h]);
                }
        }
    }

    const int erow = lane >> 2;
    const int ecol = (lane & 3) << 1;
    #pragma unroll
    for (int fm = 0; fm < 2; fm++) {
        const int r0g = row0 + wm * 32 + fm * 16 + erow;
        #pragma unroll
        for (int fn = 0; fn < 8; fn++) {
            const int cg = col0 + wn * 64 + fn * 8 + ecol;
            const float b0 = bias[cg], b1 = bias[cg + 1];
            float2 v0 = make_float2(acc[fm][fn][0] + b0, acc[fm][fn][1] + b1);
            float2 v1 = make_float2(acc[fm][fn][2] + b0, acc[fm][fn][3] + b1);
            *reinterpret_cast<float2*>(&C[(size_t)r0g * N + cg]) = v0;
            *reinterpret_cast<float2*>(&C[(size_t)(r0g + 8) * N + cg]) = v1;
        }
    }
}

// ---------------------------------------------------------------------------
// Tensor-core causal flash attention with split-bf16 (3-term) precision.
// Output written DIRECTLY in packed [hi|lo] layout for the proj GEMM.
// ---------------------------------------------------------------------------
#define ASTR  136              // bf16 elements per smem row
#define ASTRB 272              // bytes per row
#define AT_QS  0
#define AT_KS  (64 * ASTRB)
#define AT_VT  (2 * 64 * ASTRB)
#define AT_VST (3 * 64 * ASTRB)
#define ATTN_SMEM (AT_VST + 64 * 65 * 4)    // 68864 bytes

__global__ __launch_bounds__(128) void attn_mma(
    const float* __restrict__ qkv, __nv_bfloat16* __restrict__ outp)
{
    extern __shared__ __align__(16) unsigned char smraw[];
    __nv_bfloat16* Qs  = reinterpret_cast<__nv_bfloat16*>(smraw + AT_QS);
    __nv_bfloat16* Ks  = reinterpret_cast<__nv_bfloat16*>(smraw + AT_KS);
    __nv_bfloat16* Vts = reinterpret_cast<__nv_bfloat16*>(smraw + AT_VT);
    float*         Vst = reinterpret_cast<float*>(smraw + AT_VST);

    const int qt   = (gridDim.x - 1) - blockIdx.x;
    const int h    = blockIdx.y;
    const int b    = blockIdx.z;
    const int tid  = threadIdx.x;
    const int wid  = tid >> 5;
    const int lane = tid & 31;
    const int q0   = qt * 64;

    const size_t base = (size_t)b * TSEQ * THREEC;
    const int qoff = h * HD;
    const int koff = CDIM + h * HD;
    const int voff = 2 * CDIM + h * HD;

    const uint32_t QsB  = smem_u32(Qs);
    const uint32_t KsB  = smem_u32(Ks);
    const uint32_t VtsB = smem_u32(Vts);

    #pragma unroll
    for (int e = 0; e < 32; e++) {
        const int lin = e * 128 + tid;
        const int r = lin >> 6, d = lin & 63;
        const float v = qkv[base + (size_t)(q0 + r) * THREEC + qoff + d];
        const __nv_bfloat16 hi = __float2bfloat16(v);
        Qs[r * ASTR + d]      = hi;
        Qs[r * ASTR + 64 + d] = __float2bfloat16(v - __bfloat162float(hi));
    }
    __syncthreads();

    const int lrow  = lane & 15;
    const int lcolb = (lane >> 4) << 4;
    uint32_t ahi[4][4], alo[4][4];
    #pragma unroll
    for (int ks = 0; ks < 4; ks++) {
        const uint32_t ad = QsB + (uint32_t)((16 * wid + lrow) * ASTRB + ks * 32) + lcolb;
        LDSM_X4(ahi[ks][0], ahi[ks][1], ahi[ks][2], ahi[ks][3], ad);
        LDSM_X4(alo[ks][0], alo[ks][1], alo[ks][2], alo[ks][3], ad + 128);
    }

    float oacc[8][4];
    #pragma unroll
    for (int t = 0; t < 8; t++)
        #pragma unroll
        for (int j = 0; j < 4; j++) oacc[t][j] = 0.f;
    float m0r = -1.0e30f, m1r = -1.0e30f, l0 = 0.f, l1 = 0.f;

    const int   rl0   = 16 * wid + (lane >> 2);
    const int   rl1   = rl0 + 8;
    const float scale = 0.125f;

    for (int kt = 0; kt <= qt; kt++) {
        const int k0 = kt * 64;
        __syncthreads();

        #pragma unroll
        for (int e = 0; e < 32; e++) {
            const int lin = e * 128 + tid;
            const int r = lin >> 6, d = lin & 63;
            const size_t rowb = base + (size_t)(k0 + r) * THREEC;
            const float kv = qkv[rowb + koff + d];
            const __nv_bfloat16 khi = __float2bfloat16(kv);
            Ks[r * ASTR + d]      = khi;
            Ks[r * ASTR + 64 + d] = __float2bfloat16(kv - __bfloat162float(khi));
            Vst[r * 65 + d] = qkv[rowb + voff + d];
        }
        __syncthreads();

        float sf[8][4];
        #pragma unroll
        for (int t = 0; t < 8; t++)
            #pragma unroll
            for (int j = 0; j < 4; j++) sf[t][j] = 0.f;

        #pragma unroll
        for (int term = 0; term < 3; term++) {
            const uint32_t cb = (term == 1) ? 128u : 0u;
            #pragma unroll
            for (int ks = 0; ks < 4; ks++) {
                const uint32_t* af = (term == 2) ? alo[ks] : ahi[ks];
                uint32_t bq[4][4];
                #pragma unroll
                for (int g = 0; g < 4; g++) {
                    const uint32_t bd = KsB +
                        (uint32_t)((g * 16 + lrow) * ASTRB + ks * 32) + cb + lcolb;
                    LDSM_X4(bq[g][0], bq[g][1], bq[g][2], bq[g][3], bd);
                }
                #pragma unroll
                for (int g = 0; g < 4; g++)
                    #pragma unroll
                    for (int hh = 0; hh < 2; hh++) {
                        const int t = 2 * g + hh;
                        MMA_BF16(sf[t][0], sf[t][1], sf[t][2], sf[t][3],
                                 af[0], af[1], af[2], af[3],
                                 bq[g][hh], bq[g][2 + hh]);
                    }
            }
        }

        if (kt == qt) {
            #pragma unroll
            for (int t = 0; t < 8; t++) {
                const int c = t * 8 + 2 * (lane & 3);
                sf[t][0] = (c     <= rl0) ? sf[t][0] * scale : -1.0e30f;
                sf[t][1] = (c + 1 <= rl0) ? sf[t][1] * scale : -1.0e30f;
                sf[t][2] = (c     <= rl1) ? sf[t][2] * scale : -1.0e30f;
                sf[t][3] = (c + 1 <= rl1) ? sf[t][3] * scale : -1.0e30f;
            }
        } else {
            #pragma unroll
            for (int t = 0; t < 8; t++)
                #pragma unroll
                for (int j = 0; j < 4; j++) sf[t][j] *= scale;
        }

        float rm0 = -1.0e30f, rm1 = -1.0e30f;
        #pragma unroll
        for (int t = 0; t < 8; t++) {
            rm0 = fmaxf(rm0, fmaxf(sf[t][0], sf[t][1]));
            rm1 = fmaxf(rm1, fmaxf(sf[t][2], sf[t][3]));
        }
        rm0 = fmaxf(rm0, __shfl_xor_sync(0xffffffffu, rm0, 1));
        rm0 = fmaxf(rm0, __shfl_xor_sync(0xffffffffu, rm0, 2));
        rm1 = fmaxf(rm1, __shfl_xor_sync(0xffffffffu, rm1, 1));
        rm1 = fmaxf(rm1, __shfl_xor_sync(0xffffffffu, rm1, 2));
        const float mn0 = fmaxf(m0r, rm0);
        const float mn1 = fmaxf(m1r, rm1);

        float sum0 = 0.f, sum1 = 0.f;
        #pragma unroll
        for (int t = 0; t < 8; t++) {
            sf[t][0] = __expf(sf[t][0] - mn0);
            sf[t][1] = __expf(sf[t][1] - mn0);
            sf[t][2] = __expf(sf[t][2] - mn1);
            sf[t][3] = __expf(sf[t][3] - mn1);
            sum0 += sf[t][0] + sf[t][1];
            sum1 += sf[t][2] + sf[t][3];
        }
        sum0 += __shfl_xor_sync(0xffffffffu, sum0, 1);
        sum0 += __shfl_xor_sync(0xffffffffu, sum0, 2);
        sum1 += __shfl_xor_sync(0xffffffffu, sum1, 1);
        sum1 += __shfl_xor_sync(0xffffffffu, sum1, 2);

        const float al0 = __expf(m0r - mn0);
        const float al1 = __expf(m1r - mn1);
        l0 = l0 * al0 + sum0;  m0r = mn0;
        l1 = l1 * al1 + sum1;  m1r = mn1;
        #pragma unroll
        for (int t = 0; t < 8; t++) {
            oacc[t][0] *= al0; oacc[t][1] *= al0;
            oacc[t][2] *= al1; oacc[t][3] *= al1;
        }

        uint32_t phi[4][4], plo[4][4];
        #pragma unroll
        for (int ks = 0; ks < 4; ks++) {
            const float* e0 = sf[2 * ks];
            const float* e1 = sf[2 * ks + 1];
            #pragma unroll
            for (int q = 0; q < 2; q++) {
                const float* e = q ? e1 : e0;
                float hx0 = __bfloat162float(__float2bfloat16(e[0]));
                float hx1 = __bfloat162float(__float2bfloat16(e[1]));
                float hx2 = __bfloat162float(__float2bfloat16(e[2]));
                float hx3 = __bfloat162float(__float2bfloat16(e[3]));
                phi[ks][2 * q]     = pack_bf16(e[0], e[1]);
                phi[ks][2 * q + 1] = pack_bf16(e[2], e[3]);
                plo[ks][2 * q]     = pack_bf16(e[0] - hx0, e[1] - hx1);
                plo[ks][2 * q + 1] = pack_bf16(e[2] - hx2, e[3] - hx3);
            }
        }

        #pragma unroll
        for (int e = 0; e < 32; e++) {
            const int lin = e * 128 + tid;
            const int d = lin >> 6, k = lin & 63;
            const float v = Vst[k * 65 + d];
            const __nv_bfloat16 vhi = __float2bfloat16(v);
            Vts[d * ASTR + k]      = vhi;
            Vts[d * ASTR + 64 + k] = __float2bfloat16(v - __bfloat162float(vhi));
        }
        __syncthreads();

        #pragma unroll
        for (int term = 0; term < 3; term++) {
            const uint32_t cb = (term == 1) ? 128u : 0u;
            #pragma unroll
            for (int ks = 0; ks < 4; ks++) {
                const uint32_t* pf = (term == 2) ? plo[ks] : phi[ks];
                uint32_t bq[4][4];
                #pragma unroll
                for (int g = 0; g < 4; g++) {
                    const uint32_t bd = VtsB +
                        (uint32_t)((g * 16 + lrow) * ASTRB + ks * 32) + cb + lcolb;
                    LDSM_X4(bq[g][0], bq[g][1], bq[g][2], bq[g][3], bd);
                }
                #pragma unroll
                for (int g = 0; g < 4; g++)
                    #pragma unroll
                    for (int hh = 0; hh < 2; hh++) {
                        const int t = 2 * g + hh;
                        MMA_BF16(oacc[t][0], oacc[t][1], oacc[t][2], oacc[t][3],
                                 pf[0], pf[1], pf[2], pf[3],
                                 bq[g][hh], bq[g][2 + hh]);
                    }
            }
        }
    }

    // ---- Epilogue: write packed [hi|lo] directly for the proj GEMM ----
    const float inv0 = 1.0f / l0;
    const float inv1 = 1.0f / l1;
    const int r0g = q0 + rl0;
    const int r1g = q0 + rl1;
    const size_t pb0 = ((size_t)b * TSEQ + r0g) * K2 + h * HD;
    const size_t pb1 = ((size_t)b * TSEQ + r1g) * K2 + h * HD;
    #pragma unroll
    for (int t = 0; t < 8; t++) {
        const int cg = t * 8 + 2 * (lane & 3);
        const float v00 = oacc[t][0] * inv0, v01 = oacc[t][1] * inv0;
        const float v10 = oacc[t][2] * inv1, v11 = oacc[t][3] * inv1;
        const uint32_t h0 = pack_bf16(v00, v01);
        const uint32_t h1 = pack_bf16(v10, v11);
        __nv_bfloat162 h0b = *reinterpret_cast<const __nv_bfloat162*>(&h0);
        __nv_bfloat162 h1b = *reinterpret_cast<const __nv_bfloat162*>(&h1);
        const uint32_t l0p = pack_bf16(v00 - __bfloat162float(h0b.x),
                                       v01 - __bfloat162float(h0b.y));
        const uint32_t l1p = pack_bf16(v10 - __bfloat162float(h1b.x),
                                       v11 - __bfloat162float(h1b.y));
        *reinterpret_cast<uint32_t*>(&outp[pb0 + cg])        = h0;
        *reinterpret_cast<uint32_t*>(&outp[pb0 + CDIM + cg]) = l0p;
        *reinterpret_cast<uint32_t*>(&outp[pb1 + cg])        = h1;
        *reinterpret_cast<uint32_t*>(&outp[pb1 + CDIM + cg]) = l1p;
    }
}

// ---------------------------------------------------------------------------
// Launch
// ---------------------------------------------------------------------------
extern "C" void kernel_launch(void* const* d_in, const int* in_sizes, int n_in,
                              void* d_out, int out_size)
{
    const float* x     = (const float*)d_in[0];
    const float* Wqkv  = (const float*)d_in[1];
    const float* bqkv  = (const float*)d_in[2];
    const float* Wproj = (const float*)d_in[3];
    const float* bproj = (const float*)d_in[4];
    float* out = (float*)d_out;

    float *qkv;
    __nv_bfloat16 *ahat, *bqkvp, *bprojp;
    cudaGetSymbolAddress((void**)&qkv,    g_qkv);
    cudaGetSymbolAddress((void**)&ahat,   g_ahat);
    cudaGetSymbolAddress((void**)&bqkvp,  g_bqkv);
    cudaGetSymbolAddress((void**)&bprojp, g_bproj);

    cudaFuncSetAttribute(attn_mma,
                         cudaFuncAttributeMaxDynamicSharedMemorySize, ATTN_SMEM);
    cudaFuncSetAttribute(gemm_mma,
                         cudaFuncAttributeMaxDynamicSharedMemorySize, GEMM_SMEM);

    // Pack weights -> [N, 2K] = [hi|lo]
    {
        dim3 bb(32, 8);
        convert_split_wT<<<dim3(THREEC / 32, CDIM / 32), bb>>>(Wqkv, bqkvp, CDIM, THREEC);
        convert_split_wT<<<dim3(CDIM / 32, CDIM / 32), bb>>>(Wproj, bprojp, CDIM, CDIM);
    }

    // 1) Pack x and run QKV GEMM
    convert_split_act<<<(MROWS * CDIM + 255) / 256, 256>>>(x, ahat, MROWS * CDIM, CDIM);
    gemm_mma<<<dim3(THREEC / 128, MROWS / 128), 256, GEMM_SMEM>>>(
        ahat, bqkvp, bqkv, qkv, MROWS, THREEC);

    // 2) Causal attention (tensor-core, split-bf16) -> packed proj input
    attn_mma<<<dim3(TSEQ / 64, NH, BATCH), 128, ATTN_SMEM>>>(qkv, ahat);

    // 3) Output projection (reads packed attention output directly)
    gemm_mma<<<dim3(CDIM / 128, MROWS / 128), 256, GEMM_SMEM>>>(
        ahat, bprojp, bproj, out, MROWS, CDIM);
}

// round 7
// speedup vs baseline: 3.0288x; 1.2474x over previous
#include <cuda_runtime.h>
#include <cuda_bf16.h>
#include <math.h>
#include <cstdint>

// Problem constants
#define BATCH 2
#define TSEQ  2048
#define CDIM  1024
#define NH    16
#define HD    64
#define THREEC (3*CDIM)
#define MROWS (BATCH*TSEQ)   // 4096
#define K2    (2*CDIM)       // [hi|lo] packed K = 2048

// ---------------------------------------------------------------------------
// Scratch (__device__ globals; allocation-free rule)
// ---------------------------------------------------------------------------
__device__ float         g_qkv[(size_t)MROWS * THREEC];    // [B*T, 3C] fp32
__device__ __nv_bfloat16 g_ahat[(size_t)MROWS * K2];       // packed activations
__device__ __nv_bfloat16 g_bqkv[(size_t)THREEC * K2];      // packed Wqkv^T
__device__ __nv_bfloat16 g_bproj[(size_t)CDIM * K2];       // packed Wproj^T
// Pre-split attention operands
__device__ __nv_bfloat16 g_qpack[(size_t)BATCH * NH * TSEQ * 128];  // [bh][t][hi d|lo d]
__device__ __nv_bfloat16 g_kpack[(size_t)BATCH * NH * TSEQ * 128];  // [bh][t][hi d|lo d]
__device__ __nv_bfloat16 g_vpack[(size_t)BATCH * NH * HD * 2 * TSEQ]; // [bh][d][per-64-tile: hi t|lo t]

// ---------------------------------------------------------------------------
// Helpers (base-ISA only: cp.async / ldmatrix / mma.sync)
// ---------------------------------------------------------------------------
__device__ __forceinline__ uint32_t smem_u32(const void* p) {
    uint32_t a;
    asm("{ .reg .u64 t; cvta.to.shared.u64 t, %1; cvt.u32.u64 %0, t; }"
        : "=r"(a) : "l"(p));
    return a;
}
#define CP_ASYNC16(smaddr, gptr) \
    asm volatile("cp.async.cg.shared.global [%0], [%1], 16;" \
                 :: "r"(smaddr), "l"(gptr))
#define CP_COMMIT() asm volatile("cp.async.commit_group;" ::: "memory")
#define CP_WAIT(n)  asm volatile("cp.async.wait_group %0;" :: "n"(n) : "memory")

#define LDSM_X4(r0, r1, r2, r3, addr) \
    asm volatile("ldmatrix.sync.aligned.m8n8.x4.shared.b16 {%0,%1,%2,%3}, [%4];" \
                 : "=r"(r0), "=r"(r1), "=r"(r2), "=r"(r3) : "r"(addr))

#define MMA_BF16(c0, c1, c2, c3, a0, a1, a2, a3, b0, b1) \
    asm volatile("mma.sync.aligned.m16n8k16.row.col.f32.bf16.bf16.f32 " \
                 "{%0,%1,%2,%3}, {%4,%5,%6,%7}, {%8,%9}, {%0,%1,%2,%3};" \
                 : "+f"(c0), "+f"(c1), "+f"(c2), "+f"(c3) \
                 : "r"(a0), "r"(a1), "r"(a2), "r"(a3), "r"(b0), "r"(b1))

__device__ __forceinline__ uint32_t pack_bf16(float x, float y) {
    __nv_bfloat162 h = __floats2bfloat162_rn(x, y);
    return *reinterpret_cast<uint32_t*>(&h);
}

// ---------------------------------------------------------------------------
// Split-convert activations: A[M,K] fp32 -> Ahat[M,2K] bf16 = [hi | lo]
// ---------------------------------------------------------------------------
__global__ void convert_split_act(const float* __restrict__ in,
                                  __nv_bfloat16* __restrict__ out, int MK, int K)
{
    int idx = blockIdx.x * blockDim.x + threadIdx.x;
    if (idx >= MK) return;
    int m = idx / K, k = idx - m * K;
    float v = in[idx];
    __nv_bfloat16 hi = __float2bfloat16(v);
    __nv_bfloat16 lo = __float2bfloat16(v - __bfloat162float(hi));
    size_t base = (size_t)m * (2 * K);
    out[base + k]     = hi;
    out[base + K + k] = lo;
}

// ---------------------------------------------------------------------------
// Transpose + split-convert weights: W[K,N] fp32 -> Bhat[N,2K] bf16 = [hi|lo]
// ---------------------------------------------------------------------------
__global__ void convert_split_wT(const float* __restrict__ W,
                                 __nv_bfloat16* __restrict__ out, int K, int N)
{
    __shared__ float t[32][33];
    const int tx = threadIdx.x, ty = threadIdx.y;   // block (32, 8)
    const int n0 = blockIdx.x * 32, k0 = blockIdx.y * 32;
    #pragma unroll
    for (int j = 0; j < 4; j++)
        t[ty + j * 8][tx] = W[(size_t)(k0 + ty + j * 8) * N + n0 + tx];
    __syncthreads();
    #pragma unroll
    for (int j = 0; j < 4; j++) {
        const int nn = ty + j * 8;
        float v = t[tx][nn];
        __nv_bfloat16 hi = __float2bfloat16(v);
        __nv_bfloat16 lo = __float2bfloat16(v - __bfloat162float(hi));
        size_t base = (size_t)(n0 + nn) * (2 * K) + k0 + tx;
        out[base]     = hi;
        out[base + K] = lo;
    }
}

// ---------------------------------------------------------------------------
// Pre-split attention operands. Grid (TSEQ/64, NH, BATCH), block 256.
// Q is pre-scaled by 1/8. V is transposed (d-major) via smem staging.
// ---------------------------------------------------------------------------
__global__ __launch_bounds__(256) void prep_qkv(const float* __restrict__ qkv,
                                                __nv_bfloat16* __restrict__ qpack,
                                                __nv_bfloat16* __restrict__ kpack,
                                                __nv_bfloat16* __restrict__ vpack)
{
    __shared__ float vstage[64][65];
    const int tile = blockIdx.x;
    const int h    = blockIdx.y;
    const int b    = blockIdx.z;
    const int tid  = threadIdx.x;
    const int bh   = b * NH + h;
    const int t0   = tile * 64;
    const size_t base = (size_t)b * TSEQ * THREEC;

    #pragma unroll
    for (int e = 0; e < 16; e++) {
        const int lin = e * 256 + tid;
        const int r = lin >> 6, c = lin & 63;
        const size_t rowb = base + (size_t)(t0 + r) * THREEC + h * HD;
        const float qv = qkv[rowb + c] * 0.125f;          // fold softmax scale
        const float kv = qkv[rowb + CDIM + c];
        const float vv = qkv[rowb + 2 * CDIM + c];
        const __nv_bfloat16 qh = __float2bfloat16(qv);
        const __nv_bfloat16 kh = __float2bfloat16(kv);
        const size_t prow = ((size_t)bh * TSEQ + t0 + r) * 128;
        qpack[prow + c]      = qh;
        qpack[prow + 64 + c] = __float2bfloat16(qv - __bfloat162float(qh));
        kpack[prow + c]      = kh;
        kpack[prow + 64 + c] = __float2bfloat16(kv - __bfloat162float(kh));
        vstage[r][c] = vv;
    }
    __syncthreads();
    #pragma unroll
    for (int e = 0; e < 16; e++) {
        const int lin = e * 256 + tid;
        const int d = lin >> 6, c = lin & 63;      // c = token within tile
        const float v = vstage[c][d];              // banks (c+d)%32: conflict-free
        const __nv_bfloat16 vh = __float2bfloat16(v);
        const size_t vrow = ((size_t)bh * HD + d) * (2 * TSEQ) + tile * 128;
        vpack[vrow + c]      = vh;
        vpack[vrow + 64 + c] = __float2bfloat16(v - __bfloat162float(vh));
    }
}

// ---------------------------------------------------------------------------
// mma.sync bf16 GEMM (unchanged from R5 — verified)
// ---------------------------------------------------------------------------
#define GBK   32
#define NSTG  (CDIM / GBK)            // 32
#define ROWB  144
#define STAGE_BYTES (128 * ROWB)
#define STAGES 3
#define GEMM_SMEM (2 * STAGES * STAGE_BYTES)   // 110592 bytes

__global__ __launch_bounds__(256) void gemm_mma(
    const __nv_bfloat16* __restrict__ A,
    const __nv_bfloat16* __restrict__ B,
    const float* __restrict__ bias,
    float* __restrict__ C, int M, int N)
{
    extern __shared__ __align__(16) unsigned char gsm[];

    const int tid  = threadIdx.x;
    const int wid  = tid >> 5;
    const int lane = tid & 31;
    const int wm   = wid & 3;
    const int wn   = wid >> 2;
    const int row0 = blockIdx.y * 128;
    const int col0 = blockIdx.x * 128;

    const uint32_t smA_b = smem_u32(gsm);
    const uint32_t smB_b = smA_b + STAGES * STAGE_BYTES;

    const __nv_bfloat16* Arow = A + (size_t)row0 * K2;
    const __nv_bfloat16* Brow = B + (size_t)col0 * K2;

    auto load_stage = [&](int s, int buf) {
        const int k0 = s * GBK;
        const uint32_t ao = smA_b + buf * STAGE_BYTES;
        const uint32_t bo = smB_b + buf * STAGE_BYTES;
        #pragma unroll
        for (int i = 0; i < 4; i++) {
            const int idx = i * 256 + tid;
            const int r   = idx >> 3;
            const int c   = idx & 7;
            const int cc  = c & 3;
            const int gofs = (c < 4) ? (k0 + cc * 8) : (CDIM + k0 + cc * 8);
            const uint32_t so = (uint32_t)(r * ROWB + cc * 16 + ((c < 4) ? 0 : 64));
            CP_ASYNC16(ao + so, Arow + (size_t)r * K2 + gofs);
            CP_ASYNC16(bo + so, Brow + (size_t)r * K2 + gofs);
        }
    };

    float acc[2][8][4];
    #pragma unroll
    for (int i = 0; i < 2; i++)
        #pragma unroll
        for (int j = 0; j < 8; j++)
            #pragma unroll
            for (int k = 0; k < 4; k++) acc[i][j][k] = 0.f;

    const int lrow = lane & 15;
    const int lcol = (lane >> 4) << 4;

    #pragma unroll
    for (int s = 0; s < STAGES - 1; s++) { load_stage(s, s); CP_COMMIT(); }

    for (int s = 0; s < NSTG; s++) {
        CP_WAIT(STAGES - 2);
        __syncthreads();

        if (s + STAGES - 1 < NSTG)
            load_stage(s + STAGES - 1, (s + STAGES - 1) % STAGES);
        CP_COMMIT();

        const int buf = s % STAGES;
        const uint32_t aB = smA_b + buf * STAGE_BYTES;
        const uint32_t bB = smB_b + buf * STAGE_BYTES;

        #pragma unroll
        for (int ks = 0; ks < 2; ks++) {
            uint32_t ahi[2][4], alo[2][4], bhi[4][4], blo[4][4];
            #pragma unroll
            for (int fm = 0; fm < 2; fm++) {
                const uint32_t ad = aB +
                    (uint32_t)((wm * 32 + fm * 16 + lrow) * ROWB + ks * 32) + lcol;
                LDSM_X4(ahi[fm][0], ahi[fm][1], ahi[fm][2], ahi[fm][3], ad);
                LDSM_X4(alo[fm][0], alo[fm][1], alo[fm][2], alo[fm][3], ad + 64);
            }
            #pragma unroll
            for (int g = 0; g < 4; g++) {
                const uint32_t bd = bB +
                    (uint32_t)((wn * 64 + g * 16 + lrow) * ROWB + ks * 32) + lcol;
                LDSM_X4(bhi[g][0], bhi[g][1], bhi[g][2], bhi[g][3], bd);
                LDSM_X4(blo[g][0], blo[g][1], blo[g][2], blo[g][3], bd + 64);
            }
            #pragma unroll
            for (int fm = 0; fm < 2; fm++)
                #pragma unroll
                for (int fn = 0; fn < 8; fn++) {
                    const int g = fn >> 1, h = fn & 1;
                    MMA_BF16(acc[fm][fn][0], acc[fm][fn][1],
                             acc[fm][fn][2], acc[fm][fn][3],
                             ahi[fm][0], ahi[fm][1], ahi[fm][2], ahi[fm][3],
                             bhi[g][h], bhi[g][2 + h]);
                    MMA_BF16(acc[fm][fn][0], acc[fm][fn][1],
                             acc[fm][fn][2], acc[fm][fn][3],
                             ahi[fm][0], ahi[fm][1], ahi[fm][2], ahi[fm][3],
                             blo[g][h], blo[g][2 + h]);
                    MMA_BF16(acc[fm][fn][0], acc[fm][fn][1],
                             acc[fm][fn][2], acc[fm][fn][3],
                             alo[fm][0], alo[fm][1], alo[fm][2], alo[fm][3],
                             bhi[g][h], bhi[g][2 + h]);
                }
        }
    }

    const int erow = lane >> 2;
    const int ecol = (lane & 3) << 1;
    #pragma unroll
    for (int fm = 0; fm < 2; fm++) {
        const int r0g = row0 + wm * 32 + fm * 16 + erow;
        #pragma unroll
        for (int fn = 0; fn < 8; fn++) {
            const int cg = col0 + wn * 64 + fn * 8 + ecol;
            const float b0 = bias[cg], b1 = bias[cg + 1];
            float2 v0 = make_float2(acc[fm][fn][0] + b0, acc[fm][fn][1] + b1);
            float2 v1 = make_float2(acc[fm][fn][2] + b0, acc[fm][fn][3] + b1);
            *reinterpret_cast<float2*>(&C[(size_t)r0g * N + cg]) = v0;
            *reinterpret_cast<float2*>(&C[(size_t)(r0g + 8) * N + cg]) = v1;
        }
    }
}

// ---------------------------------------------------------------------------
// Tensor-core causal flash attention, pre-split operands, cp.async pipelined.
// 128 threads (4 warps), 64 q-rows/CTA. Double-buffered K/V tiles.
// ---------------------------------------------------------------------------
#define ASTR  136              // bf16 elements per smem row
#define ASTRB 272              // bytes per row
#define TILEB (64 * ASTRB)     // 17408 per tile buffer
#define AT_QS  0
#define AT_KS  TILEB                       // K double buffer
#define AT_VS  (AT_KS + 2 * TILEB)         // V double buffer
#define ATTN_SMEM (AT_VS + 2 * TILEB)      // 87040 bytes

__global__ __launch_bounds__(128) void attn_mma(
    const __nv_bfloat16* __restrict__ qpack,
    const __nv_bfloat16* __restrict__ kpack,
    const __nv_bfloat16* __restrict__ vpack,
    __nv_bfloat16* __restrict__ outp)
{
    extern __shared__ __align__(16) unsigned char smraw[];

    const int qt   = (gridDim.x - 1) - blockIdx.x;   // heavy tiles first
    const int h    = blockIdx.y;
    const int b    = blockIdx.z;
    const int tid  = threadIdx.x;
    const int wid  = tid >> 5;
    const int lane = tid & 31;
    const int q0   = qt * 64;
    const int bh   = b * NH + h;

    const uint32_t QsB = smem_u32(smraw);
    const uint32_t KsB = QsB + AT_KS;
    const uint32_t VsB = QsB + AT_VS;

    const __nv_bfloat16* qrows = qpack + ((size_t)bh * TSEQ + q0) * 128;
    const __nv_bfloat16* krows = kpack + (size_t)bh * TSEQ * 128;
    const __nv_bfloat16* vrows = vpack + (size_t)bh * HD * (2 * TSEQ);

    // K tile kt: 64 rows of 256B from krows + (kt*64+r)*128 elems
    // V tile kt: 64 d-rows of 256B from vrows + d*4096 + kt*128 elems
    auto load_kv = [&](int kt, int buf) {
        const uint32_t kdst = KsB + buf * TILEB;
        const uint32_t vdst = VsB + buf * TILEB;
        #pragma unroll
        for (int i = 0; i < 8; i++) {
            const int idx = i * 128 + tid;      // 0..1023
            const int r = idx >> 4;             // 0..63
            const int c = idx & 15;             // 16B chunk
            CP_ASYNC16(kdst + (uint32_t)(r * ASTRB + c * 16),
                       krows + ((size_t)(kt * 64 + r)) * 128 + c * 8);
            CP_ASYNC16(vdst + (uint32_t)(r * ASTRB + c * 16),
                       vrows + (size_t)r * (2 * TSEQ) + kt * 128 + c * 8);
        }
    };

    // Prologue: Q + first K/V tile
    #pragma unroll
    for (int i = 0; i < 8; i++) {
        const int idx = i * 128 + tid;
        const int r = idx >> 4;
        const int c = idx & 15;
        CP_ASYNC16(QsB + (uint32_t)(r * ASTRB + c * 16),
                   qrows + (size_t)r * 128 + c * 8);
    }
    load_kv(0, 0);
    CP_COMMIT();
    CP_WAIT(0);
    __syncthreads();

    // Q fragments
    const int lrow  = lane & 15;
    const int lcolb = (lane >> 4) << 4;
    uint32_t ahi[4][4], alo[4][4];
    #pragma unroll
    for (int ks = 0; ks < 4; ks++) {
        const uint32_t ad = QsB + (uint32_t)((16 * wid + lrow) * ASTRB + ks * 32) + lcolb;
        LDSM_X4(ahi[ks][0], ahi[ks][1], ahi[ks][2], ahi[ks][3], ad);
        LDSM_X4(alo[ks][0], alo[ks][1], alo[ks][2], alo[ks][3], ad + 128);
    }

    float oacc[8][4];
    #pragma unroll
    for (int t = 0; t < 8; t++)
        #pragma unroll
        for (int j = 0; j < 4; j++) oacc[t][j] = 0.f;
    float m0r = -1.0e30f, m1r = -1.0e30f, l0 = 0.f, l1 = 0.f;

    const int rl0 = 16 * wid + (lane >> 2);
    const int rl1 = rl0 + 8;

    for (int kt = 0; kt <= qt; kt++) {
        // Prefetch next tile (other buffer is safe: sync at end of prev iter)
        if (kt < qt) { load_kv(kt + 1, (kt + 1) & 1); CP_COMMIT(); }

        const uint32_t kB = KsB + (kt & 1) * TILEB;
        const uint32_t vB = VsB + (kt & 1) * TILEB;

        // ---- S = Qhat . Khat^T  (load hi/lo once; 3 MMAs per fragment) ----
        float sf[8][4];
        #pragma unroll
        for (int t = 0; t < 8; t++)
            #pragma unroll
            for (int j = 0; j < 4; j++) sf[t][j] = 0.f;

        #pragma unroll
        for (int ks = 0; ks < 4; ks++) {
            uint32_t bhi[4][4], blo[4][4];
            #pragma unroll
            for (int g = 0; g < 4; g++) {
                const uint32_t bd = kB +
                    (uint32_t)((g * 16 + lrow) * ASTRB + ks * 32) + lcolb;
                LDSM_X4(bhi[g][0], bhi[g][1], bhi[g][2], bhi[g][3], bd);
                LDSM_X4(blo[g][0], blo[g][1], blo[g][2], blo[g][3], bd + 128);
            }
            #pragma unroll
            for (int g = 0; g < 4; g++)
                #pragma unroll
                for (int hh = 0; hh < 2; hh++) {
                    const int t = 2 * g + hh;
                    MMA_BF16(sf[t][0], sf[t][1], sf[t][2], sf[t][3],
                             ahi[ks][0], ahi[ks][1], ahi[ks][2], ahi[ks][3],
                             bhi[g][hh], bhi[g][2 + hh]);
                    MMA_BF16(sf[t][0], sf[t][1], sf[t][2], sf[t][3],
                             ahi[ks][0], ahi[ks][1], ahi[ks][2], ahi[ks][3],
                             blo[g][hh], blo[g][2 + hh]);
                    MMA_BF16(sf[t][0], sf[t][1], sf[t][2], sf[t][3],
                             alo[ks][0], alo[ks][1], alo[ks][2], alo[ks][3],
                             bhi[g][hh], bhi[g][2 + hh]);
                }
        }

        // ---- Causal mask (scale already folded into Q) ----
        if (kt == qt) {
            #pragma unroll
            for (int t = 0; t < 8; t++) {
                const int c = t * 8 + 2 * (lane & 3);
                if (c     > rl0) sf[t][0] = -1.0e30f;
                if (c + 1 > rl0) sf[t][1] = -1.0e30f;
                if (c     > rl1) sf[t][2] = -1.0e30f;
                if (c + 1 > rl1) sf[t][3] = -1.0e30f;
            }
        }

        // ---- Online softmax ----
        float rm0 = -1.0e30f, rm1 = -1.0e30f;
        #pragma unroll
        for (int t = 0; t < 8; t++) {
            rm0 = fmaxf(rm0, fmaxf(sf[t][0], sf[t][1]));
            rm1 = fmaxf(rm1, fmaxf(sf[t][2], sf[t][3]));
        }
        rm0 = fmaxf(rm0, __shfl_xor_sync(0xffffffffu, rm0, 1));
        rm0 = fmaxf(rm0, __shfl_xor_sync(0xffffffffu, rm0, 2));
        rm1 = fmaxf(rm1, __shfl_xor_sync(0xffffffffu, rm1, 1));
        rm1 = fmaxf(rm1, __shfl_xor_sync(0xffffffffu, rm1, 2));
        const float mn0 = fmaxf(m0r, rm0);
        const float mn1 = fmaxf(m1r, rm1);

        float sum0 = 0.f, sum1 = 0.f;
        #pragma unroll
        for (int t = 0; t < 8; t++) {
            sf[t][0] = __expf(sf[t][0] - mn0);
            sf[t][1] = __expf(sf[t][1] - mn0);
            sf[t][2] = __expf(sf[t][2] - mn1);
            sf[t][3] = __expf(sf[t][3] - mn1);
            sum0 += sf[t][0] + sf[t][1];
            sum1 += sf[t][2] + sf[t][3];
        }
        sum0 += __shfl_xor_sync(0xffffffffu, sum0, 1);
        sum0 += __shfl_xor_sync(0xffffffffu, sum0, 2);
        sum1 += __shfl_xor_sync(0xffffffffu, sum1, 1);
        sum1 += __shfl_xor_sync(0xffffffffu, sum1, 2);

        const float al0 = __expf(m0r - mn0);
        const float al1 = __expf(m1r - mn1);
        l0 = l0 * al0 + sum0;  m0r = mn0;
        l1 = l1 * al1 + sum1;  m1r = mn1;
        #pragma unroll
        for (int t = 0; t < 8; t++) {
            oacc[t][0] *= al0; oacc[t][1] *= al0;
            oacc[t][2] *= al1; oacc[t][3] *= al1;
        }

        // ---- P fragments (hi/lo split, registers only) ----
        uint32_t phi[4][4], plo[4][4];
        #pragma unroll
        for (int ks = 0; ks < 4; ks++) {
            const float* e0 = sf[2 * ks];
            const float* e1 = sf[2 * ks + 1];
            #pragma unroll
            for (int q = 0; q < 2; q++) {
                const float* e = q ? e1 : e0;
                float hx0 = __bfloat162float(__float2bfloat16(e[0]));
                float hx1 = __bfloat162float(__float2bfloat16(e[1]));
                float hx2 = __bfloat162float(__float2bfloat16(e[2]));
                float hx3 = __bfloat162float(__float2bfloat16(e[3]));
                phi[ks][2 * q]     = pack_bf16(e[0], e[1]);
                phi[ks][2 * q + 1] = pack_bf16(e[2], e[3]);
                plo[ks][2 * q]     = pack_bf16(e[0] - hx0, e[1] - hx1);
                plo[ks][2 * q + 1] = pack_bf16(e[2] - hx2, e[3] - hx3);
            }
        }

        // ---- O += Phat . Vthat^T ----
        #pragma unroll
        for (int ks = 0; ks < 4; ks++) {
            uint32_t bhi[4][4], blo[4][4];
            #pragma unroll
            for (int g = 0; g < 4; g++) {
                const uint32_t bd = vB +
                    (uint32_t)((g * 16 + lrow) * ASTRB + ks * 32) + lcolb;
                LDSM_X4(bhi[g][0], bhi[g][1], bhi[g][2], bhi[g][3], bd);
                LDSM_X4(blo[g][0], blo[g][1], blo[g][2], blo[g][3], bd + 128);
            }
            #pragma unroll
            for (int g = 0; g < 4; g++)
                #pragma unroll
                for (int hh = 0; hh < 2; hh++) {
                    const int t = 2 * g + hh;
                    MMA_BF16(oacc[t][0], oacc[t][1], oacc[t][2], oacc[t][3],
                             phi[ks][0], phi[ks][1], phi[ks][2], phi[ks][3],
                             bhi[g][hh], bhi[g][2 + hh]);
                    MMA_BF16(oacc[t][0], oacc[t][1], oacc[t][2], oacc[t][3],
                             phi[ks][0], phi[ks][1], phi[ks][2], phi[ks][3],
                             blo[g][hh], blo[g][2 + hh]);
                    MMA_BF16(oacc[t][0], oacc[t][1], oacc[t][2], oacc[t][3],
                             plo[ks][0], plo[ks][1], plo[ks][2], plo[ks][3],
                             bhi[g][hh], bhi[g][2 + hh]);
                }
        }

        if (kt < qt) {
            CP_WAIT(0);          // next tile resident
            __syncthreads();     // all warps done with current buffers
        }
    }

    // ---- Epilogue: packed [hi|lo] proj input ----
    const float inv0 = 1.0f / l0;
    const float inv1 = 1.0f / l1;
    const int r0g = q0 + rl0;
    const int r1g = q0 + rl1;
    const size_t pb0 = ((size_t)b * TSEQ + r0g) * K2 + h * HD;
    const size_t pb1 = ((size_t)b * TSEQ + r1g) * K2 + h * HD;
    #pragma unroll
    for (int t = 0; t < 8; t++) {
        const int cg = t * 8 + 2 * (lane & 3);
        const float v00 = oacc[t][0] * inv0, v01 = oacc[t][1] * inv0;
        const float v10 = oacc[t][2] * inv1, v11 = oacc[t][3] * inv1;
        const uint32_t h0 = pack_bf16(v00, v01);
        const uint32_t h1 = pack_bf16(v10, v11);
        __nv_bfloat162 h0b = *reinterpret_cast<const __nv_bfloat162*>(&h0);
        __nv_bfloat162 h1b = *reinterpret_cast<const __nv_bfloat162*>(&h1);
        const uint32_t l0p = pack_bf16(v00 - __bfloat162float(h0b.x),
                                       v01 - __bfloat162float(h0b.y));
        const uint32_t l1p = pack_bf16(v10 - __bfloat162float(h1b.x),
                                       v11 - __bfloat162float(h1b.y));
        *reinterpret_cast<uint32_t*>(&outp[pb0 + cg])        = h0;
        *reinterpret_cast<uint32_t*>(&outp[pb0 + CDIM + cg]) = l0p;
        *reinterpret_cast<uint32_t*>(&outp[pb1 + cg])        = h1;
        *reinterpret_cast<uint32_t*>(&outp[pb1 + CDIM + cg]) = l1p;
    }
}

// ---------------------------------------------------------------------------
// Launch
// ---------------------------------------------------------------------------
extern "C" void kernel_launch(void* const* d_in, const int* in_sizes, int n_in,
                              void* d_out, int out_size)
{
    const float* x     = (const float*)d_in[0];
    const float* Wqkv  = (const float*)d_in[1];
    const float* bqkv  = (const float*)d_in[2];
    const float* Wproj = (const float*)d_in[3];
    const float* bproj = (const float*)d_in[4];
    float* out = (float*)d_out;

    float *qkv;
    __nv_bfloat16 *ahat, *bqkvp, *bprojp, *qp, *kp, *vp;
    cudaGetSymbolAddress((void**)&qkv,    g_qkv);
    cudaGetSymbolAddress((void**)&ahat,   g_ahat);
    cudaGetSymbolAddress((void**)&bqkvp,  g_bqkv);
    cudaGetSymbolAddress((void**)&bprojp, g_bproj);
    cudaGetSymbolAddress((void**)&qp,     g_qpack);
    cudaGetSymbolAddress((void**)&kp,     g_kpack);
    cudaGetSymbolAddress((void**)&vp,     g_vpack);

    cudaFuncSetAttribute(attn_mma,
                         cudaFuncAttributeMaxDynamicSharedMemorySize, ATTN_SMEM);
    cudaFuncSetAttribute(gemm_mma,
                         cudaFuncAttributeMaxDynamicSharedMemorySize, GEMM_SMEM);

    // Pack weights -> [N, 2K] = [hi|lo]
    {
        dim3 bb(32, 8);
        convert_split_wT<<<dim3(THREEC / 32, CDIM / 32), bb>>>(Wqkv, bqkvp, CDIM, THREEC);
        convert_split_wT<<<dim3(CDIM / 32, CDIM / 32), bb>>>(Wproj, bprojp, CDIM, CDIM);
    }

    // 1) Pack x and run QKV GEMM
    convert_split_act<<<(MROWS * CDIM + 255) / 256, 256>>>(x, ahat, MROWS * CDIM, CDIM);
    gemm_mma<<<dim3(THREEC / 128, MROWS / 128), 256, GEMM_SMEM>>>(
        ahat, bqkvp, bqkv, qkv, MROWS, THREEC);

    // 2) Pre-split Q/K/V once, then pipelined attention -> packed proj input
    prep_qkv<<<dim3(TSEQ / 64, NH, BATCH), 256>>>(qkv, qp, kp, vp);
    attn_mma<<<dim3(TSEQ / 64, NH, BATCH), 128, ATTN_SMEM>>>(qp, kp, vp, ahat);

    // 3) Output projection
    gemm_mma<<<dim3(CDIM / 128, MROWS / 128), 256, GEMM_SMEM>>>(
        ahat, bprojp, bproj, out, MROWS, CDIM);
}

// round 8
// speedup vs baseline: 3.0414x; 1.0042x over previous
#include <cuda_runtime.h>
#include <cuda_bf16.h>
#include <math.h>
#include <cstdint>

// Problem constants
#define BATCH 2
#define TSEQ  2048
#define CDIM  1024
#define NH    16
#define HD    64
#define THREEC (3*CDIM)
#define MROWS (BATCH*TSEQ)   // 4096
#define K2    (2*CDIM)       // [hi|lo] packed K = 2048

// ---------------------------------------------------------------------------
// Scratch (__device__ globals; allocation-free rule)
// ---------------------------------------------------------------------------
__device__ float         g_qkv[(size_t)MROWS * THREEC];    // [B*T, 3C] fp32
__device__ __nv_bfloat16 g_ahat[(size_t)MROWS * K2];       // packed activations
__device__ __nv_bfloat16 g_bqkv[(size_t)THREEC * K2];      // packed Wqkv^T
__device__ __nv_bfloat16 g_bproj[(size_t)CDIM * K2];       // packed Wproj^T
// Pre-split attention operands
__device__ __nv_bfloat16 g_qpack[(size_t)BATCH * NH * TSEQ * 128];
__device__ __nv_bfloat16 g_kpack[(size_t)BATCH * NH * TSEQ * 128];
__device__ __nv_bfloat16 g_vpack[(size_t)BATCH * NH * HD * 2 * TSEQ];

// ---------------------------------------------------------------------------
// Helpers (base-ISA only: cp.async / ldmatrix / mma.sync)
// ---------------------------------------------------------------------------
__device__ __forceinline__ uint32_t smem_u32(const void* p) {
    uint32_t a;
    asm("{ .reg .u64 t; cvta.to.shared.u64 t, %1; cvt.u32.u64 %0, t; }"
        : "=r"(a) : "l"(p));
    return a;
}
#define CP_ASYNC16(smaddr, gptr) \
    asm volatile("cp.async.cg.shared.global [%0], [%1], 16;" \
                 :: "r"(smaddr), "l"(gptr))
#define CP_COMMIT() asm volatile("cp.async.commit_group;" ::: "memory")
#define CP_WAIT(n)  asm volatile("cp.async.wait_group %0;" :: "n"(n) : "memory")

#define LDSM_X4(r0, r1, r2, r3, addr) \
    asm volatile("ldmatrix.sync.aligned.m8n8.x4.shared.b16 {%0,%1,%2,%3}, [%4];" \
                 : "=r"(r0), "=r"(r1), "=r"(r2), "=r"(r3) : "r"(addr))

#define MMA_BF16(c0, c1, c2, c3, a0, a1, a2, a3, b0, b1) \
    asm volatile("mma.sync.aligned.m16n8k16.row.col.f32.bf16.bf16.f32 " \
                 "{%0,%1,%2,%3}, {%4,%5,%6,%7}, {%8,%9}, {%0,%1,%2,%3};" \
                 : "+f"(c0), "+f"(c1), "+f"(c2), "+f"(c3) \
                 : "r"(a0), "r"(a1), "r"(a2), "r"(a3), "r"(b0), "r"(b1))

__device__ __forceinline__ uint32_t pack_bf16(float x, float y) {
    __nv_bfloat162 h = __floats2bfloat162_rn(x, y);
    return *reinterpret_cast<uint32_t*>(&h);
}

// ---------------------------------------------------------------------------
// Split-convert activations: A[M,K] fp32 -> Ahat[M,2K] bf16 = [hi | lo]
// ---------------------------------------------------------------------------
__global__ void convert_split_act(const float* __restrict__ in,
                                  __nv_bfloat16* __restrict__ out, int MK, int K)
{
    int idx = blockIdx.x * blockDim.x + threadIdx.x;
    if (idx >= MK) return;
    int m = idx / K, k = idx - m * K;
    float v = in[idx];
    __nv_bfloat16 hi = __float2bfloat16(v);
    __nv_bfloat16 lo = __float2bfloat16(v - __bfloat162float(hi));
    size_t base = (size_t)m * (2 * K);
    out[base + k]     = hi;
    out[base + K + k] = lo;
}

// ---------------------------------------------------------------------------
// Transpose + split-convert weights: W[K,N] fp32 -> Bhat[N,2K] bf16 = [hi|lo]
// ---------------------------------------------------------------------------
__global__ void convert_split_wT(const float* __restrict__ W,
                                 __nv_bfloat16* __restrict__ out, int K, int N)
{
    __shared__ float t[32][33];
    const int tx = threadIdx.x, ty = threadIdx.y;   // block (32, 8)
    const int n0 = blockIdx.x * 32, k0 = blockIdx.y * 32;
    #pragma unroll
    for (int j = 0; j < 4; j++)
        t[ty + j * 8][tx] = W[(size_t)(k0 + ty + j * 8) * N + n0 + tx];
    __syncthreads();
    #pragma unroll
    for (int j = 0; j < 4; j++) {
        const int nn = ty + j * 8;
        float v = t[tx][nn];
        __nv_bfloat16 hi = __float2bfloat16(v);
        __nv_bfloat16 lo = __float2bfloat16(v - __bfloat162float(hi));
        size_t base = (size_t)(n0 + nn) * (2 * K) + k0 + tx;
        out[base]     = hi;
        out[base + K] = lo;
    }
}

// ---------------------------------------------------------------------------
// Pre-split attention operands (unchanged from R6 — verified)
// ---------------------------------------------------------------------------
__global__ __launch_bounds__(256) void prep_qkv(const float* __restrict__ qkv,
                                                __nv_bfloat16* __restrict__ qpack,
                                                __nv_bfloat16* __restrict__ kpack,
                                                __nv_bfloat16* __restrict__ vpack)
{
    __shared__ float vstage[64][65];
    const int tile = blockIdx.x;
    const int h    = blockIdx.y;
    const int b    = blockIdx.z;
    const int tid  = threadIdx.x;
    const int bh   = b * NH + h;
    const int t0   = tile * 64;
    const size_t base = (size_t)b * TSEQ * THREEC;

    #pragma unroll
    for (int e = 0; e < 16; e++) {
        const int lin = e * 256 + tid;
        const int r = lin >> 6, c = lin & 63;
        const size_t rowb = base + (size_t)(t0 + r) * THREEC + h * HD;
        const float qv = qkv[rowb + c] * 0.125f;
        const float kv = qkv[rowb + CDIM + c];
        const float vv = qkv[rowb + 2 * CDIM + c];
        const __nv_bfloat16 qh = __float2bfloat16(qv);
        const __nv_bfloat16 kh = __float2bfloat16(kv);
        const size_t prow = ((size_t)bh * TSEQ + t0 + r) * 128;
        qpack[prow + c]      = qh;
        qpack[prow + 64 + c] = __float2bfloat16(qv - __bfloat162float(qh));
        kpack[prow + c]      = kh;
        kpack[prow + 64 + c] = __float2bfloat16(kv - __bfloat162float(kh));
        vstage[r][c] = vv;
    }
    __syncthreads();
    #pragma unroll
    for (int e = 0; e < 16; e++) {
        const int lin = e * 256 + tid;
        const int d = lin >> 6, c = lin & 63;
        const float v = vstage[c][d];
        const __nv_bfloat16 vh = __float2bfloat16(v);
        const size_t vrow = ((size_t)bh * HD + d) * (2 * TSEQ) + tile * 128;
        vpack[vrow + c]      = vh;
        vpack[vrow + 64 + c] = __float2bfloat16(v - __bfloat162float(vh));
    }
}

// ---------------------------------------------------------------------------
// mma.sync bf16 GEMM, [hi|lo] + register 3-term split.
// STAGES=2 double buffer -> 73.7KB smem -> 3 CTAs/SM (24 warps).
// Order per stage: wait-all -> sync -> issue next load -> compute.
// ---------------------------------------------------------------------------
#define GBK   32
#define NSTG  (CDIM / GBK)            // 32
#define ROWB  144
#define STAGE_BYTES (128 * ROWB)      // 18432
#define STAGES 2
#define GEMM_SMEM (2 * STAGES * STAGE_BYTES)   // 73728 bytes

__global__ __launch_bounds__(256) void gemm_mma(
    const __nv_bfloat16* __restrict__ A,
    const __nv_bfloat16* __restrict__ B,
    const float* __restrict__ bias,
    float* __restrict__ C, int M, int N)
{
    extern __shared__ __align__(16) unsigned char gsm[];

    const int tid  = threadIdx.x;
    const int wid  = tid >> 5;
    const int lane = tid & 31;
    const int wm   = wid & 3;
    const int wn   = wid >> 2;
    const int row0 = blockIdx.y * 128;
    const int col0 = blockIdx.x * 128;

    const uint32_t smA_b = smem_u32(gsm);
    const uint32_t smB_b = smA_b + STAGES * STAGE_BYTES;

    const __nv_bfloat16* Arow = A + (size_t)row0 * K2;
    const __nv_bfloat16* Brow = B + (size_t)col0 * K2;

    auto load_stage = [&](int s, int buf) {
        const int k0 = s * GBK;
        const uint32_t ao = smA_b + buf * STAGE_BYTES;
        const uint32_t bo = smB_b + buf * STAGE_BYTES;
        #pragma unroll
        for (int i = 0; i < 4; i++) {
            const int idx = i * 256 + tid;
            const int r   = idx >> 3;
            const int c   = idx & 7;
            const int cc  = c & 3;
            const int gofs = (c < 4) ? (k0 + cc * 8) : (CDIM + k0 + cc * 8);
            const uint32_t so = (uint32_t)(r * ROWB + cc * 16 + ((c < 4) ? 0 : 64));
            CP_ASYNC16(ao + so, Arow + (size_t)r * K2 + gofs);
            CP_ASYNC16(bo + so, Brow + (size_t)r * K2 + gofs);
        }
    };

    float acc[2][8][4];
    #pragma unroll
    for (int i = 0; i < 2; i++)
        #pragma unroll
        for (int j = 0; j < 8; j++)
            #pragma unroll
            for (int k = 0; k < 4; k++) acc[i][j][k] = 0.f;

    const int lrow = lane & 15;
    const int lcol = (lane >> 4) << 4;

    load_stage(0, 0);
    CP_COMMIT();

    for (int s = 0; s < NSTG; s++) {
        CP_WAIT(0);              // stage s resident (overlapped compute s-1)
        __syncthreads();         // all warps done with buf (s-1)&1 == (s+1)&1

        if (s + 1 < NSTG) {      // safe now: everyone left buf (s+1)&1
            load_stage(s + 1, (s + 1) & 1);
            CP_COMMIT();
        }

        const int buf = s & 1;
        const uint32_t aB = smA_b + buf * STAGE_BYTES;
        const uint32_t bB = smB_b + buf * STAGE_BYTES;

        #pragma unroll
        for (int ks = 0; ks < 2; ks++) {
            uint32_t ahi[2][4], alo[2][4], bhi[4][4], blo[4][4];
            #pragma unroll
            for (int fm = 0; fm < 2; fm++) {
                const uint32_t ad = aB +
                    (uint32_t)((wm * 32 + fm * 16 + lrow) * ROWB + ks * 32) + lcol;
                LDSM_X4(ahi[fm][0], ahi[fm][1], ahi[fm][2], ahi[fm][3], ad);
                LDSM_X4(alo[fm][0], alo[fm][1], alo[fm][2], alo[fm][3], ad + 64);
            }
            #pragma unroll
            for (int g = 0; g < 4; g++) {
                const uint32_t bd = bB +
                    (uint32_t)((wn * 64 + g * 16 + lrow) * ROWB + ks * 32) + lcol;
                LDSM_X4(bhi[g][0], bhi[g][1], bhi[g][2], bhi[g][3], bd);
                LDSM_X4(blo[g][0], blo[g][1], blo[g][2], blo[g][3], bd + 64);
            }
            #pragma unroll
            for (int fm = 0; fm < 2; fm++)
                #pragma unroll
                for (int fn = 0; fn < 8; fn++) {
                    const int g = fn >> 1, h = fn & 1;
                    MMA_BF16(acc[fm][fn][0], acc[fm][fn][1],
                             acc[fm][fn][2], acc[fm][fn][3],
                             ahi[fm][0], ahi[fm][1], ahi[fm][2], ahi[fm][3],
                             bhi[g][h], bhi[g][2 + h]);
                    MMA_BF16(acc[fm][fn][0], acc[fm][fn][1],
                             acc[fm][fn][2], acc[fm][fn][3],
                             ahi[fm][0], ahi[fm][1], ahi[fm][2], ahi[fm][3],
                             blo[g][h], blo[g][2 + h]);
                    MMA_BF16(acc[fm][fn][0], acc[fm][fn][1],
                             acc[fm][fn][2], acc[fm][fn][3],
                             alo[fm][0], alo[fm][1], alo[fm][2], alo[fm][3],
                             bhi[g][h], bhi[g][2 + h]);
                }
        }
    }

    const int erow = lane >> 2;
    const int ecol = (lane & 3) << 1;
    #pragma unroll
    for (int fm = 0; fm < 2; fm++) {
        const int r0g = row0 + wm * 32 + fm * 16 + erow;
        #pragma unroll
        for (int fn = 0; fn < 8; fn++) {
            const int cg = col0 + wn * 64 + fn * 8 + ecol;
            const float b0 = bias[cg], b1 = bias[cg + 1];
            float2 v0 = make_float2(acc[fm][fn][0] + b0, acc[fm][fn][1] + b1);
            float2 v1 = make_float2(acc[fm][fn][2] + b0, acc[fm][fn][3] + b1);
            *reinterpret_cast<float2*>(&C[(size_t)r0g * N + cg]) = v0;
            *reinterpret_cast<float2*>(&C[(size_t)(r0g + 8) * N + cg]) = v1;
        }
    }
}

// ---------------------------------------------------------------------------
// Tensor-core causal flash attention, pre-split operands, cp.async pipelined.
// Q tile overlaid on K-buf1 (dead after fragment load): 69.6KB -> 3 CTAs/SM.
// ---------------------------------------------------------------------------
#define ASTR  136
#define ASTRB 272
#define TILEB (64 * ASTRB)                 // 17408
#define ATTN_SMEM (4 * TILEB)              // 69632 bytes

__global__ __launch_bounds__(128) void attn_mma(
    const __nv_bfloat16* __restrict__ qpack,
    const __nv_bfloat16* __restrict__ kpack,
    const __nv_bfloat16* __restrict__ vpack,
    __nv_bfloat16* __restrict__ outp)
{
    extern __shared__ __align__(16) unsigned char smraw[];

    const int qt   = (gridDim.x - 1) - blockIdx.x;
    const int h    = blockIdx.y;
    const int b    = blockIdx.z;
    const int tid  = threadIdx.x;
    const int wid  = tid >> 5;
    const int lane = tid & 31;
    const int q0   = qt * 64;
    const int bh   = b * NH + h;

    // Layout: [K0 | K1/Q | V0 | V1]
    const uint32_t KsB = smem_u32(smraw);
    const uint32_t QsB = KsB + TILEB;            // Q staged in K-buf1
    const uint32_t VsB = KsB + 2 * TILEB;

    const __nv_bfloat16* qrows = qpack + ((size_t)bh * TSEQ + q0) * 128;
    const __nv_bfloat16* krows = kpack + (size_t)bh * TSEQ * 128;
    const __nv_bfloat16* vrows = vpack + (size_t)bh * HD * (2 * TSEQ);

    auto load_kv = [&](int kt, int buf) {
        const uint32_t kdst = KsB + buf * TILEB;
        const uint32_t vdst = VsB + buf * TILEB;
        #pragma unroll
        for (int i = 0; i < 8; i++) {
            const int idx = i * 128 + tid;
            const int r = idx >> 4;
            const int c = idx & 15;
            CP_ASYNC16(kdst + (uint32_t)(r * ASTRB + c * 16),
                       krows + ((size_t)(kt * 64 + r)) * 128 + c * 8);
            CP_ASYNC16(vdst + (uint32_t)(r * ASTRB + c * 16),
                       vrows + (size_t)r * (2 * TSEQ) + kt * 128 + c * 8);
        }
    };

    // Prologue: Q (into K1 slot) + first K/V tile
    #pragma unroll
    for (int i = 0; i < 8; i++) {
        const int idx = i * 128 + tid;
        const int r = idx >> 4;
        const int c = idx & 15;
        CP_ASYNC16(QsB + (uint32_t)(r * ASTRB + c * 16),
                   qrows + (size_t)r * 128 + c * 8);
    }
    load_kv(0, 0);
    CP_COMMIT();
    CP_WAIT(0);
    __syncthreads();

    // Q fragments (after this, the Q smem region is dead)
    const int lrow  = lane & 15;
    const int lcolb = (lane >> 4) << 4;
    uint32_t ahi[4][4], alo[4][4];
    #pragma unroll
    for (int ks = 0; ks < 4; ks++) {
        const uint32_t ad = QsB + (uint32_t)((16 * wid + lrow) * ASTRB + ks * 32) + lcolb;
        LDSM_X4(ahi[ks][0], ahi[ks][1], ahi[ks][2], ahi[ks][3], ad);
        LDSM_X4(alo[ks][0], alo[ks][1], alo[ks][2], alo[ks][3], ad + 128);
    }
    __syncthreads();   // all warps done reading Q before kt=1 prefetch reuses K1

    float oacc[8][4];
    #pragma unroll
    for (int t = 0; t < 8; t++)
        #pragma unroll
        for (int j = 0; j < 4; j++) oacc[t][j] = 0.f;
    float m0r = -1.0e30f, m1r = -1.0e30f, l0 = 0.f, l1 = 0.f;

    const int rl0 = 16 * wid + (lane >> 2);
    const int rl1 = rl0 + 8;

    for (int kt = 0; kt <= qt; kt++) {
        if (kt < qt) { load_kv(kt + 1, (kt + 1) & 1); CP_COMMIT(); }

        const uint32_t kB = KsB + (kt & 1) * TILEB;
        const uint32_t vB = VsB + (kt & 1) * TILEB;

        float sf[8][4];
        #pragma unroll
        for (int t = 0; t < 8; t++)
            #pragma unroll
            for (int j = 0; j < 4; j++) sf[t][j] = 0.f;

        #pragma unroll
        for (int ks = 0; ks < 4; ks++) {
            uint32_t bhi[4][4], blo[4][4];
            #pragma unroll
            for (int g = 0; g < 4; g++) {
                const uint32_t bd = kB +
                    (uint32_t)((g * 16 + lrow) * ASTRB + ks * 32) + lcolb;
                LDSM_X4(bhi[g][0], bhi[g][1], bhi[g][2], bhi[g][3], bd);
                LDSM_X4(blo[g][0], blo[g][1], blo[g][2], blo[g][3], bd + 128);
            }
            #pragma unroll
            for (int g = 0; g < 4; g++)
                #pragma unroll
                for (int hh = 0; hh < 2; hh++) {
                    const int t = 2 * g + hh;
                    MMA_BF16(sf[t][0], sf[t][1], sf[t][2], sf[t][3],
                             ahi[ks][0], ahi[ks][1], ahi[ks][2], ahi[ks][3],
                             bhi[g][hh], bhi[g][2 + hh]);
                    MMA_BF16(sf[t][0], sf[t][1], sf[t][2], sf[t][3],
                             ahi[ks][0], ahi[ks][1], ahi[ks][2], ahi[ks][3],
                             blo[g][hh], blo[g][2 + hh]);
                    MMA_BF16(sf[t][0], sf[t][1], sf[t][2], sf[t][3],
                             alo[ks][0], alo[ks][1], alo[ks][2], alo[ks][3],
                             bhi[g][hh], bhi[g][2 + hh]);
                }
        }

        if (kt == qt) {
            #pragma unroll
            for (int t = 0; t < 8; t++) {
                const int c = t * 8 + 2 * (lane & 3);
                if (c     > rl0) sf[t][0] = -1.0e30f;
                if (c + 1 > rl0) sf[t][1] = -1.0e30f;
                if (c     > rl1) sf[t][2] = -1.0e30f;
                if (c + 1 > rl1) sf[t][3] = -1.0e30f;
            }
        }

        float rm0 = -1.0e30f, rm1 = -1.0e30f;
        #pragma unroll
        for (int t = 0; t < 8; t++) {
            rm0 = fmaxf(rm0, fmaxf(sf[t][0], sf[t][1]));
            rm1 = fmaxf(rm1, fmaxf(sf[t][2], sf[t][3]));
        }
        rm0 = fmaxf(rm0, __shfl_xor_sync(0xffffffffu, rm0, 1));
        rm0 = fmaxf(rm0, __shfl_xor_sync(0xffffffffu, rm0, 2));
        rm1 = fmaxf(rm1, __shfl_xor_sync(0xffffffffu, rm1, 1));
        rm1 = fmaxf(rm1, __shfl_xor_sync(0xffffffffu, rm1, 2));
        const float mn0 = fmaxf(m0r, rm0);
        const float mn1 = fmaxf(m1r, rm1);

        float sum0 = 0.f, sum1 = 0.f;
        #pragma unroll
        for (int t = 0; t < 8; t++) {
            sf[t][0] = __expf(sf[t][0] - mn0);
            sf[t][1] = __expf(sf[t][1] - mn0);
            sf[t][2] = __expf(sf[t][2] - mn1);
            sf[t][3] = __expf(sf[t][3] - mn1);
            sum0 += sf[t][0] + sf[t][1];
            sum1 += sf[t][2] + sf[t][3];
        }
        sum0 += __shfl_xor_sync(0xffffffffu, sum0, 1);
        sum0 += __shfl_xor_sync(0xffffffffu, sum0, 2);
        sum1 += __shfl_xor_sync(0xffffffffu, sum1, 1);
        sum1 += __shfl_xor_sync(0xffffffffu, sum1, 2);

        const float al0 = __expf(m0r - mn0);
        const float al1 = __expf(m1r - mn1);
        l0 = l0 * al0 + sum0;  m0r = mn0;
        l1 = l1 * al1 + sum1;  m1r = mn1;
        #pragma unroll
        for (int t = 0; t < 8; t++) {
            oacc[t][0] *= al0; oacc[t][1] *= al0;
            oacc[t][2] *= al1; oacc[t][3] *= al1;
        }

        uint32_t phi[4][4], plo[4][4];
        #pragma unroll
        for (int ks = 0; ks < 4; ks++) {
            const float* e0 = sf[2 * ks];
            const float* e1 = sf[2 * ks + 1];
            #pragma unroll
            for (int q = 0; q < 2; q++) {
                const float* e = q ? e1 : e0;
                float hx0 = __bfloat162float(__float2bfloat16(e[0]));
                float hx1 = __bfloat162float(__float2bfloat16(e[1]));
                float hx2 = __bfloat162float(__float2bfloat16(e[2]));
                float hx3 = __bfloat162float(__float2bfloat16(e[3]));
                phi[ks][2 * q]     = pack_bf16(e[0], e[1]);
                phi[ks][2 * q + 1] = pack_bf16(e[2], e[3]);
                plo[ks][2 * q]     = pack_bf16(e[0] - hx0, e[1] - hx1);
                plo[ks][2 * q + 1] = pack_bf16(e[2] - hx2, e[3] - hx3);
            }
        }

        #pragma unroll
        for (int ks = 0; ks < 4; ks++) {
            uint32_t bhi[4][4], blo[4][4];
            #pragma unroll
            for (int g = 0; g < 4; g++) {
                const uint32_t bd = vB +
                    (uint32_t)((g * 16 + lrow) * ASTRB + ks * 32) + lcolb;
                LDSM_X4(bhi[g][0], bhi[g][1], bhi[g][2], bhi[g][3], bd);
                LDSM_X4(blo[g][0], blo[g][1], blo[g][2], blo[g][3], bd + 128);
            }
            #pragma unroll
            for (int g = 0; g < 4; g++)
                #pragma unroll
                for (int hh = 0; hh < 2; hh++) {
                    const int t = 2 * g + hh;
                    MMA_BF16(oacc[t][0], oacc[t][1], oacc[t][2], oacc[t][3],
                             phi[ks][0], phi[ks][1], phi[ks][2], phi[ks][3],
                             bhi[g][hh], bhi[g][2 + hh]);
                    MMA_BF16(oacc[t][0], oacc[t][1], oacc[t][2], oacc[t][3],
                             phi[ks][0], phi[ks][1], phi[ks][2], phi[ks][3],
                             blo[g][hh], blo[g][2 + hh]);
                    MMA_BF16(oacc[t][0], oacc[t][1], oacc[t][2], oacc[t][3],
                             plo[ks][0], plo[ks][1], plo[ks][2], plo[ks][3],
                             bhi[g][hh], bhi[g][2 + hh]);
                }
        }

        if (kt < qt) {
            CP_WAIT(0);
            __syncthreads();
        }
    }

    // ---- Epilogue: packed [hi|lo] proj input ----
    const float inv0 = 1.0f / l0;
    const float inv1 = 1.0f / l1;
    const int r0g = q0 + rl0;
    const int r1g = q0 + rl1;
    const size_t pb0 = ((size_t)b * TSEQ + r0g) * K2 + h * HD;
    const size_t pb1 = ((size_t)b * TSEQ + r1g) * K2 + h * HD;
    #pragma unroll
    for (int t = 0; t < 8; t++) {
        const int cg = t * 8 + 2 * (lane & 3);
        const float v00 = oacc[t][0] * inv0, v01 = oacc[t][1] * inv0;
        const float v10 = oacc[t][2] * inv1, v11 = oacc[t][3] * inv1;
        const uint32_t h0 = pack_bf16(v00, v01);
        const uint32_t h1 = pack_bf16(v10, v11);
        __nv_bfloat162 h0b = *reinterpret_cast<const __nv_bfloat162*>(&h0);
        __nv_bfloat162 h1b = *reinterpret_cast<const __nv_bfloat162*>(&h1);
        const uint32_t l0p = pack_bf16(v00 - __bfloat162float(h0b.x),
                                       v01 - __bfloat162float(h0b.y));
        const uint32_t l1p = pack_bf16(v10 - __bfloat162float(h1b.x),
                                       v11 - __bfloat162float(h1b.y));
        *reinterpret_cast<uint32_t*>(&outp[pb0 + cg])        = h0;
        *reinterpret_cast<uint32_t*>(&outp[pb0 + CDIM + cg]) = l0p;
        *reinterpret_cast<uint32_t*>(&outp[pb1 + cg])        = h1;
        *reinterpret_cast<uint32_t*>(&outp[pb1 + CDIM + cg]) = l1p;
    }
}

// ---------------------------------------------------------------------------
// Launch
// ---------------------------------------------------------------------------
extern "C" void kernel_launch(void* const* d_in, const int* in_sizes, int n_in,
                              void* d_out, int out_size)
{
    const float* x     = (const float*)d_in[0];
    const float* Wqkv  = (const float*)d_in[1];
    const float* bqkv  = (const float*)d_in[2];
    const float* Wproj = (const float*)d_in[3];
    const float* bproj = (const float*)d_in[4];
    float* out = (float*)d_out;

    float *qkv;
    __nv_bfloat16 *ahat, *bqkvp, *bprojp, *qp, *kp, *vp;
    cudaGetSymbolAddress((void**)&qkv,    g_qkv);
    cudaGetSymbolAddress((void**)&ahat,   g_ahat);
    cudaGetSymbolAddress((void**)&bqkvp,  g_bqkv);
    cudaGetSymbolAddress((void**)&bprojp, g_bproj);
    cudaGetSymbolAddress((void**)&qp,     g_qpack);
    cudaGetSymbolAddress((void**)&kp,     g_kpack);
    cudaGetSymbolAddress((void**)&vp,     g_vpack);

    cudaFuncSetAttribute(attn_mma,
                         cudaFuncAttributeMaxDynamicSharedMemorySize, ATTN_SMEM);
    cudaFuncSetAttribute(gemm_mma,
                         cudaFuncAttributeMaxDynamicSharedMemorySize, GEMM_SMEM);

    // Pack weights -> [N, 2K] = [hi|lo]
    {
        dim3 bb(32, 8);
        convert_split_wT<<<dim3(THREEC / 32, CDIM / 32), bb>>>(Wqkv, bqkvp, CDIM, THREEC);
        convert_split_wT<<<dim3(CDIM / 32, CDIM / 32), bb>>>(Wproj, bprojp, CDIM, CDIM);
    }

    // 1) Pack x and run QKV GEMM
    convert_split_act<<<(MROWS * CDIM + 255) / 256, 256>>>(x, ahat, MROWS * CDIM, CDIM);
    gemm_mma<<<dim3(THREEC / 128, MROWS / 128), 256, GEMM_SMEM>>>(
        ahat, bqkvp, bqkv, qkv, MROWS, THREEC);

    // 2) Pre-split Q/K/V once, then pipelined attention -> packed proj input
    prep_qkv<<<dim3(TSEQ / 64, NH, BATCH), 256>>>(qkv, qp, kp, vp);
    attn_mma<<<dim3(TSEQ / 64, NH, BATCH), 128, ATTN_SMEM>>>(qp, kp, vp, ahat);

    // 3) Output projection
    gemm_mma<<<dim3(CDIM / 128, MROWS / 128), 256, GEMM_SMEM>>>(
        ahat, bprojp, bproj, out, MROWS, CDIM);
}

// round 9
// speedup vs baseline: 3.1036x; 1.0205x over previous
#include <cuda_runtime.h>
#include <cuda_bf16.h>
#include <math.h>
#include <cstdint>

// Problem constants
#define BATCH 2
#define TSEQ  2048
#define CDIM  1024
#define NH    16
#define HD    64
#define THREEC (3*CDIM)
#define MROWS (BATCH*TSEQ)   // 4096
#define K2    (2*CDIM)       // [hi|lo] packed K = 2048

// ---------------------------------------------------------------------------
// Scratch (__device__ globals; allocation-free rule)
// ---------------------------------------------------------------------------
__device__ __nv_bfloat16 g_ahat[(size_t)MROWS * K2];       // packed activations
__device__ __nv_bfloat16 g_bqkv[(size_t)THREEC * K2];      // packed Wqkv^T
__device__ __nv_bfloat16 g_bproj[(size_t)CDIM * K2];       // packed Wproj^T
// Pre-split attention operands (written directly by the QKV GEMM epilogue)
__device__ __nv_bfloat16 g_qpack[(size_t)BATCH * NH * TSEQ * 128];
__device__ __nv_bfloat16 g_kpack[(size_t)BATCH * NH * TSEQ * 128];
__device__ __nv_bfloat16 g_vpack[(size_t)BATCH * NH * HD * 2 * TSEQ];

// ---------------------------------------------------------------------------
// Helpers (base-ISA only: cp.async / ldmatrix / mma.sync)
// ---------------------------------------------------------------------------
__device__ __forceinline__ uint32_t smem_u32(const void* p) {
    uint32_t a;
    asm("{ .reg .u64 t; cvta.to.shared.u64 t, %1; cvt.u32.u64 %0, t; }"
        : "=r"(a) : "l"(p));
    return a;
}
#define CP_ASYNC16(smaddr, gptr) \
    asm volatile("cp.async.cg.shared.global [%0], [%1], 16;" \
                 :: "r"(smaddr), "l"(gptr))
#define CP_COMMIT() asm volatile("cp.async.commit_group;" ::: "memory")
#define CP_WAIT(n)  asm volatile("cp.async.wait_group %0;" :: "n"(n) : "memory")

#define LDSM_X4(r0, r1, r2, r3, addr) \
    asm volatile("ldmatrix.sync.aligned.m8n8.x4.shared.b16 {%0,%1,%2,%3}, [%4];" \
                 : "=r"(r0), "=r"(r1), "=r"(r2), "=r"(r3) : "r"(addr))

#define MMA_BF16(c0, c1, c2, c3, a0, a1, a2, a3, b0, b1) \
    asm volatile("mma.sync.aligned.m16n8k16.row.col.f32.bf16.bf16.f32 " \
                 "{%0,%1,%2,%3}, {%4,%5,%6,%7}, {%8,%9}, {%0,%1,%2,%3};" \
                 : "+f"(c0), "+f"(c1), "+f"(c2), "+f"(c3) \
                 : "r"(a0), "r"(a1), "r"(a2), "r"(a3), "r"(b0), "r"(b1))

__device__ __forceinline__ uint32_t pack_bf16(float x, float y) {
    __nv_bfloat162 h = __floats2bfloat162_rn(x, y);
    return *reinterpret_cast<uint32_t*>(&h);
}

// ---------------------------------------------------------------------------
// Split-convert activations: A[M,K] fp32 -> Ahat[M,2K] bf16 = [hi | lo]
// ---------------------------------------------------------------------------
__global__ void convert_split_act(const float* __restrict__ in,
                                  __nv_bfloat16* __restrict__ out, int MK, int K)
{
    int idx = blockIdx.x * blockDim.x + threadIdx.x;
    if (idx >= MK) return;
    int m = idx / K, k = idx - m * K;
    float v = in[idx];
    __nv_bfloat16 hi = __float2bfloat16(v);
    __nv_bfloat16 lo = __float2bfloat16(v - __bfloat162float(hi));
    size_t base = (size_t)m * (2 * K);
    out[base + k]     = hi;
    out[base + K + k] = lo;
}

// ---------------------------------------------------------------------------
// Transpose + split-convert weights: W[K,N] fp32 -> Bhat[N,2K] bf16 = [hi|lo]
// ---------------------------------------------------------------------------
__global__ void convert_split_wT(const float* __restrict__ W,
                                 __nv_bfloat16* __restrict__ out, int K, int N)
{
    __shared__ float t[32][33];
    const int tx = threadIdx.x, ty = threadIdx.y;   // block (32, 8)
    const int n0 = blockIdx.x * 32, k0 = blockIdx.y * 32;
    #pragma unroll
    for (int j = 0; j < 4; j++)
        t[ty + j * 8][tx] = W[(size_t)(k0 + ty + j * 8) * N + n0 + tx];
    __syncthreads();
    #pragma unroll
    for (int j = 0; j < 4; j++) {
        const int nn = ty + j * 8;
        float v = t[tx][nn];
        __nv_bfloat16 hi = __float2bfloat16(v);
        __nv_bfloat16 lo = __float2bfloat16(v - __bfloat162float(hi));
        size_t base = (size_t)(n0 + nn) * (2 * K) + k0 + tx;
        out[base]     = hi;
        out[base + K] = lo;
    }
}

// ---------------------------------------------------------------------------
// Shared GEMM mainloop config
// ---------------------------------------------------------------------------
#define GBK   32
#define NSTG  (CDIM / GBK)            // 32
#define ROWB  144
#define STAGE_BYTES (128 * ROWB)      // 18432
#define STAGES 2
#define GEMM_SMEM (2 * STAGES * STAGE_BYTES)   // 73728 bytes

// Mainloop macro body (identical compute for both GEMM variants).
// Defines acc[2][8][4] and runs the full K loop.
#define GEMM_MAINLOOP(Aptr, Bptr)                                              \
    extern __shared__ __align__(16) unsigned char gsm[];                       \
    const int tid  = threadIdx.x;                                              \
    const int wid  = tid >> 5;                                                 \
    const int lane = tid & 31;                                                 \
    const int wm   = wid & 3;                                                  \
    const int wn   = wid >> 2;                                                 \
    const int row0 = blockIdx.y * 128;                                         \
    const int col0 = blockIdx.x * 128;                                         \
    const uint32_t smA_b = smem_u32(gsm);                                      \
    const uint32_t smB_b = smA_b + STAGES * STAGE_BYTES;                       \
    const __nv_bfloat16* Arow = (Aptr) + (size_t)row0 * K2;                    \
    const __nv_bfloat16* Brow = (Bptr) + (size_t)col0 * K2;                    \
    auto load_stage = [&](int s, int buf) {                                    \
        const int k0 = s * GBK;                                                \
        const uint32_t ao = smA_b + buf * STAGE_BYTES;                         \
        const uint32_t bo = smB_b + buf * STAGE_BYTES;                         \
        _Pragma("unroll")                                                      \
        for (int i = 0; i < 4; i++) {                                          \
            const int idx = i * 256 + tid;                                     \
            const int r   = idx >> 3;                                          \
            const int c   = idx & 7;                                           \
            const int cc  = c & 3;                                             \
            const int gofs = (c < 4) ? (k0 + cc * 8) : (CDIM + k0 + cc * 8);   \
            const uint32_t so = (uint32_t)(r * ROWB + cc * 16 + ((c < 4) ? 0 : 64)); \
            CP_ASYNC16(ao + so, Arow + (size_t)r * K2 + gofs);                 \
            CP_ASYNC16(bo + so, Brow + (size_t)r * K2 + gofs);                 \
        }                                                                      \
    };                                                                         \
    float acc[2][8][4];                                                        \
    _Pragma("unroll")                                                          \
    for (int i = 0; i < 2; i++)                                                \
        _Pragma("unroll")                                                      \
        for (int j = 0; j < 8; j++)                                            \
            _Pragma("unroll")                                                  \
            for (int k = 0; k < 4; k++) acc[i][j][k] = 0.f;                    \
    const int lrow = lane & 15;                                                \
    const int lcol = (lane >> 4) << 4;                                         \
    load_stage(0, 0);                                                          \
    CP_COMMIT();                                                               \
    for (int s = 0; s < NSTG; s++) {                                           \
        CP_WAIT(0);                                                            \
        __syncthreads();                                                       \
        if (s + 1 < NSTG) { load_stage(s + 1, (s + 1) & 1); CP_COMMIT(); }     \
        const int buf = s & 1;                                                 \
        const uint32_t aB = smA_b + buf * STAGE_BYTES;                         \
        const uint32_t bB = smB_b + buf * STAGE_BYTES;                         \
        _Pragma("unroll")                                                      \
        for (int ks = 0; ks < 2; ks++) {                                       \
            uint32_t ahi[2][4], alo[2][4], bhi[4][4], blo[4][4];               \
            _Pragma("unroll")                                                  \
            for (int fm = 0; fm < 2; fm++) {                                   \
                const uint32_t ad = aB +                                       \
                    (uint32_t)((wm * 32 + fm * 16 + lrow) * ROWB + ks * 32) + lcol; \
                LDSM_X4(ahi[fm][0], ahi[fm][1], ahi[fm][2], ahi[fm][3], ad);   \
                LDSM_X4(alo[fm][0], alo[fm][1], alo[fm][2], alo[fm][3], ad + 64); \
            }                                                                  \
            _Pragma("unroll")                                                  \
            for (int g = 0; g < 4; g++) {                                      \
                const uint32_t bd = bB +                                       \
                    (uint32_t)((wn * 64 + g * 16 + lrow) * ROWB + ks * 32) + lcol; \
                LDSM_X4(bhi[g][0], bhi[g][1], bhi[g][2], bhi[g][3], bd);       \
                LDSM_X4(blo[g][0], blo[g][1], blo[g][2], blo[g][3], bd + 64);  \
            }                                                                  \
            _Pragma("unroll")                                                  \
            for (int fm = 0; fm < 2; fm++)                                     \
                _Pragma("unroll")                                              \
                for (int fn = 0; fn < 8; fn++) {                               \
                    const int g = fn >> 1, h = fn & 1;                         \
                    MMA_BF16(acc[fm][fn][0], acc[fm][fn][1],                   \
                             acc[fm][fn][2], acc[fm][fn][3],                   \
                             ahi[fm][0], ahi[fm][1], ahi[fm][2], ahi[fm][3],   \
                             bhi[g][h], bhi[g][2 + h]);                        \
                    MMA_BF16(acc[fm][fn][0], acc[fm][fn][1],                   \
                             acc[fm][fn][2], acc[fm][fn][3],                   \
                             ahi[fm][0], ahi[fm][1], ahi[fm][2], ahi[fm][3],   \
                             blo[g][h], blo[g][2 + h]);                        \
                    MMA_BF16(acc[fm][fn][0], acc[fm][fn][1],                   \
                             acc[fm][fn][2], acc[fm][fn][3],                   \
                             alo[fm][0], alo[fm][1], alo[fm][2], alo[fm][3],   \
                             bhi[g][h], bhi[g][2 + h]);                        \
                }                                                              \
        }                                                                      \
    }

// ---------------------------------------------------------------------------
// Proj GEMM: plain fp32 output + bias (unchanged behavior, verified)
// ---------------------------------------------------------------------------
__global__ __launch_bounds__(256) void gemm_mma(
    const __nv_bfloat16* __restrict__ A,
    const __nv_bfloat16* __restrict__ B,
    const float* __restrict__ bias,
    float* __restrict__ C, int M, int N)
{
    GEMM_MAINLOOP(A, B)

    const int erow = lane >> 2;
    const int ecol = (lane & 3) << 1;
    #pragma unroll
    for (int fm = 0; fm < 2; fm++) {
        const int r0g = row0 + wm * 32 + fm * 16 + erow;
        #pragma unroll
        for (int fn = 0; fn < 8; fn++) {
            const int cg = col0 + wn * 64 + fn * 8 + ecol;
            const float b0 = bias[cg], b1 = bias[cg + 1];
            float2 v0 = make_float2(acc[fm][fn][0] + b0, acc[fm][fn][1] + b1);
            float2 v1 = make_float2(acc[fm][fn][2] + b0, acc[fm][fn][3] + b1);
            *reinterpret_cast<float2*>(&C[(size_t)r0g * N + cg]) = v0;
            *reinterpret_cast<float2*>(&C[(size_t)(r0g + 8) * N + cg]) = v1;
        }
    }
}

// ---------------------------------------------------------------------------
// QKV GEMM with fused pack epilogue: writes qpack/kpack (token-major, hi|lo)
// and vpack (d-major transposed, hi|lo) directly from registers.
// Column section (Q/K/V) and head are per-warp constants.
// ---------------------------------------------------------------------------
__global__ __launch_bounds__(256) void gemm_qkv(
    const __nv_bfloat16* __restrict__ A,
    const __nv_bfloat16* __restrict__ B,
    const float* __restrict__ bias,
    __nv_bfloat16* __restrict__ qpack,
    __nv_bfloat16* __restrict__ kpack,
    __nv_bfloat16* __restrict__ vpack)
{
    GEMM_MAINLOOP(A, B)

    const int erow = lane >> 2;
    const int ecol = (lane & 3) << 1;
    const int sec  = col0 >> 10;                      // 0=Q 1=K 2=V (tile never crosses)
    const int hh   = ((col0 & 1023) >> 6) + wn;       // head (per-warp constant)
    const float scale = (sec == 0) ? 0.125f : 1.0f;   // fold softmax scale into Q

    #pragma unroll
    for (int fm = 0; fm < 2; fm++) {
        const int t0g = row0 + wm * 32 + fm * 16 + erow;   // token row (acc .,.,0/1)
        const int bidx = t0g >> 11;                        // same for t0g+8 (tiles 128-aligned)
        const int bh   = bidx * NH + hh;
        const int tl0  = t0g & 2047;
        const int tl1  = tl0 + 8;                          // acc .,.,2/3
        #pragma unroll
        for (int fn = 0; fn < 8; fn++) {
            const int cg = col0 + wn * 64 + fn * 8 + ecol;
            const int d  = (cg & 63);                      // d, d+1 within head
            const float b0 = bias[cg], b1 = bias[cg + 1];
            const float v00 = (acc[fm][fn][0] + b0) * scale;
            const float v01 = (acc[fm][fn][1] + b1) * scale;
            const float v10 = (acc[fm][fn][2] + b0) * scale;
            const float v11 = (acc[fm][fn][3] + b1) * scale;

            const uint32_t h0 = pack_bf16(v00, v01);
            const uint32_t h1 = pack_bf16(v10, v11);
            const __nv_bfloat162 h0b = *reinterpret_cast<const __nv_bfloat162*>(&h0);
            const __nv_bfloat162 h1b = *reinterpret_cast<const __nv_bfloat162*>(&h1);
            const uint32_t l0 = pack_bf16(v00 - __bfloat162float(h0b.x),
                                          v01 - __bfloat162float(h0b.y));
            const uint32_t l1 = pack_bf16(v10 - __bfloat162float(h1b.x),
                                          v11 - __bfloat162float(h1b.y));

            if (sec < 2) {
                __nv_bfloat16* dst = (sec == 0) ? qpack : kpack;
                const size_t r0 = ((size_t)bh * TSEQ + tl0) * 128 + d;
                const size_t r1 = ((size_t)bh * TSEQ + tl1) * 128 + d;
                *reinterpret_cast<uint32_t*>(&dst[r0])      = h0;
                *reinterpret_cast<uint32_t*>(&dst[r0 + 64]) = l0;
                *reinterpret_cast<uint32_t*>(&dst[r1])      = h1;
                *reinterpret_cast<uint32_t*>(&dst[r1 + 64]) = l1;
            } else {
                // V transposed: vpack[bh][d][tile*128 + (hi: tl%64 | lo: 64 + tl%64)]
                #pragma unroll
                for (int dd = 0; dd < 2; dd++) {
                    const size_t vb = ((size_t)bh * HD + d + dd) * (2 * TSEQ);
                    const size_t c0 = vb + (tl0 >> 6) * 128 + (tl0 & 63);
                    const size_t c1 = vb + (tl1 >> 6) * 128 + (tl1 & 63);
                    const float e0 = dd ? v01 : v00;
                    const float e1 = dd ? v11 : v10;
                    const __nv_bfloat16 e0h = __float2bfloat16(e0);
                    const __nv_bfloat16 e1h = __float2bfloat16(e1);
                    vpack[c0]      = e0h;
                    vpack[c0 + 64] = __float2bfloat16(e0 - __bfloat162float(e0h));
                    vpack[c1]      = e1h;
                    vpack[c1 + 64] = __float2bfloat16(e1 - __bfloat162float(e1h));
                }
            }
        }
    }
}

// ---------------------------------------------------------------------------
// Tensor-core causal flash attention (unchanged from R7 — verified)
// ---------------------------------------------------------------------------
#define ASTR  136
#define ASTRB 272
#define TILEB (64 * ASTRB)                 // 17408
#define ATTN_SMEM (4 * TILEB)              // 69632 bytes

__global__ __launch_bounds__(128) void attn_mma(
    const __nv_bfloat16* __restrict__ qpack,
    const __nv_bfloat16* __restrict__ kpack,
    const __nv_bfloat16* __restrict__ vpack,
    __nv_bfloat16* __restrict__ outp)
{
    extern __shared__ __align__(16) unsigned char smraw[];

    const int qt   = (gridDim.x - 1) - blockIdx.x;
    const int h    = blockIdx.y;
    const int b    = blockIdx.z;
    const int tid  = threadIdx.x;
    const int wid  = tid >> 5;
    const int lane = tid & 31;
    const int q0   = qt * 64;
    const int bh   = b * NH + h;

    const uint32_t KsB = smem_u32(smraw);
    const uint32_t QsB = KsB + TILEB;            // Q staged in K-buf1
    const uint32_t VsB = KsB + 2 * TILEB;

    const __nv_bfloat16* qrows = qpack + ((size_t)bh * TSEQ + q0) * 128;
    const __nv_bfloat16* krows = kpack + (size_t)bh * TSEQ * 128;
    const __nv_bfloat16* vrows = vpack + (size_t)bh * HD * (2 * TSEQ);

    auto load_kv = [&](int kt, int buf) {
        const uint32_t kdst = KsB + buf * TILEB;
        const uint32_t vdst = VsB + buf * TILEB;
        #pragma unroll
        for (int i = 0; i < 8; i++) {
            const int idx = i * 128 + tid;
            const int r = idx >> 4;
            const int c = idx & 15;
            CP_ASYNC16(kdst + (uint32_t)(r * ASTRB + c * 16),
                       krows + ((size_t)(kt * 64 + r)) * 128 + c * 8);
            CP_ASYNC16(vdst + (uint32_t)(r * ASTRB + c * 16),
                       vrows + (size_t)r * (2 * TSEQ) + kt * 128 + c * 8);
        }
    };

    #pragma unroll
    for (int i = 0; i < 8; i++) {
        const int idx = i * 128 + tid;
        const int r = idx >> 4;
        const int c = idx & 15;
        CP_ASYNC16(QsB + (uint32_t)(r * ASTRB + c * 16),
                   qrows + (size_t)r * 128 + c * 8);
    }
    load_kv(0, 0);
    CP_COMMIT();
    CP_WAIT(0);
    __syncthreads();

    const int lrow  = lane & 15;
    const int lcolb = (lane >> 4) << 4;
    uint32_t ahi[4][4], alo[4][4];
    #pragma unroll
    for (int ks = 0; ks < 4; ks++) {
        const uint32_t ad = QsB + (uint32_t)((16 * wid + lrow) * ASTRB + ks * 32) + lcolb;
        LDSM_X4(ahi[ks][0], ahi[ks][1], ahi[ks][2], ahi[ks][3], ad);
        LDSM_X4(alo[ks][0], alo[ks][1], alo[ks][2], alo[ks][3], ad + 128);
    }
    __syncthreads();

    float oacc[8][4];
    #pragma unroll
    for (int t = 0; t < 8; t++)
        #pragma unroll
        for (int j = 0; j < 4; j++) oacc[t][j] = 0.f;
    float m0r = -1.0e30f, m1r = -1.0e30f, l0 = 0.f, l1 = 0.f;

    const int rl0 = 16 * wid + (lane >> 2);
    const int rl1 = rl0 + 8;

    for (int kt = 0; kt <= qt; kt++) {
        if (kt < qt) { load_kv(kt + 1, (kt + 1) & 1); CP_COMMIT(); }

        const uint32_t kB = KsB + (kt & 1) * TILEB;
        const uint32_t vB = VsB + (kt & 1) * TILEB;

        float sf[8][4];
        #pragma unroll
        for (int t = 0; t < 8; t++)
            #pragma unroll
            for (int j = 0; j < 4; j++) sf[t][j] = 0.f;

        #pragma unroll
        for (int ks = 0; ks < 4; ks++) {
            uint32_t bhi[4][4], blo[4][4];
            #pragma unroll
            for (int g = 0; g < 4; g++) {
                const uint32_t bd = kB +
                    (uint32_t)((g * 16 + lrow) * ASTRB + ks * 32) + lcolb;
                LDSM_X4(bhi[g][0], bhi[g][1], bhi[g][2], bhi[g][3], bd);
                LDSM_X4(blo[g][0], blo[g][1], blo[g][2], blo[g][3], bd + 128);
            }
            #pragma unroll
            for (int g = 0; g < 4; g++)
                #pragma unroll
                for (int hh = 0; hh < 2; hh++) {
                    const int t = 2 * g + hh;
                    MMA_BF16(sf[t][0], sf[t][1], sf[t][2], sf[t][3],
                             ahi[ks][0], ahi[ks][1], ahi[ks][2], ahi[ks][3],
                             bhi[g][hh], bhi[g][2 + hh]);
                    MMA_BF16(sf[t][0], sf[t][1], sf[t][2], sf[t][3],
                             ahi[ks][0], ahi[ks][1], ahi[ks][2], ahi[ks][3],
                             blo[g][hh], blo[g][2 + hh]);
                    MMA_BF16(sf[t][0], sf[t][1], sf[t][2], sf[t][3],
                             alo[ks][0], alo[ks][1], alo[ks][2], alo[ks][3],
                             bhi[g][hh], bhi[g][2 + hh]);
                }
        }

        if (kt == qt) {
            #pragma unroll
            for (int t = 0; t < 8; t++) {
                const int c = t * 8 + 2 * (lane & 3);
                if (c     > rl0) sf[t][0] = -1.0e30f;
                if (c + 1 > rl0) sf[t][1] = -1.0e30f;
                if (c     > rl1) sf[t][2] = -1.0e30f;
                if (c + 1 > rl1) sf[t][3] = -1.0e30f;
            }
        }

        float rm0 = -1.0e30f, rm1 = -1.0e30f;
        #pragma unroll
        for (int t = 0; t < 8; t++) {
            rm0 = fmaxf(rm0, fmaxf(sf[t][0], sf[t][1]));
            rm1 = fmaxf(rm1, fmaxf(sf[t][2], sf[t][3]));
        }
        rm0 = fmaxf(rm0, __shfl_xor_sync(0xffffffffu, rm0, 1));
        rm0 = fmaxf(rm0, __shfl_xor_sync(0xffffffffu, rm0, 2));
        rm1 = fmaxf(rm1, __shfl_xor_sync(0xffffffffu, rm1, 1));
        rm1 = fmaxf(rm1, __shfl_xor_sync(0xffffffffu, rm1, 2));
        const float mn0 = fmaxf(m0r, rm0);
        const float mn1 = fmaxf(m1r, rm1);

        float sum0 = 0.f, sum1 = 0.f;
        #pragma unroll
        for (int t = 0; t < 8; t++) {
            sf[t][0] = __expf(sf[t][0] - mn0);
            sf[t][1] = __expf(sf[t][1] - mn0);
            sf[t][2] = __expf(sf[t][2] - mn1);
            sf[t][3] = __expf(sf[t][3] - mn1);
            sum0 += sf[t][0] + sf[t][1];
            sum1 += sf[t][2] + sf[t][3];
        }
        sum0 += __shfl_xor_sync(0xffffffffu, sum0, 1);
        sum0 += __shfl_xor_sync(0xffffffffu, sum0, 2);
        sum1 += __shfl_xor_sync(0xffffffffu, sum1, 1);
        sum1 += __shfl_xor_sync(0xffffffffu, sum1, 2);

        const float al0 = __expf(m0r - mn0);
        const float al1 = __expf(m1r - mn1);
        l0 = l0 * al0 + sum0;  m0r = mn0;
        l1 = l1 * al1 + sum1;  m1r = mn1;
        #pragma unroll
        for (int t = 0; t < 8; t++) {
            oacc[t][0] *= al0; oacc[t][1] *= al0;
            oacc[t][2] *= al1; oacc[t][3] *= al1;
        }

        uint32_t phi[4][4], plo[4][4];
        #pragma unroll
        for (int ks = 0; ks < 4; ks++) {
            const float* e0 = sf[2 * ks];
            const float* e1 = sf[2 * ks + 1];
            #pragma unroll
            for (int q = 0; q < 2; q++) {
                const float* e = q ? e1 : e0;
                float hx0 = __bfloat162float(__float2bfloat16(e[0]));
                float hx1 = __bfloat162float(__float2bfloat16(e[1]));
                float hx2 = __bfloat162float(__float2bfloat16(e[2]));
                float hx3 = __bfloat162float(__float2bfloat16(e[3]));
                phi[ks][2 * q]     = pack_bf16(e[0], e[1]);
                phi[ks][2 * q + 1] = pack_bf16(e[2], e[3]);
                plo[ks][2 * q]     = pack_bf16(e[0] - hx0, e[1] - hx1);
                plo[ks][2 * q + 1] = pack_bf16(e[2] - hx2, e[3] - hx3);
            }
        }

        #pragma unroll
        for (int ks = 0; ks < 4; ks++) {
            uint32_t bhi[4][4], blo[4][4];
            #pragma unroll
            for (int g = 0; g < 4; g++) {
                const uint32_t bd = vB +
                    (uint32_t)((g * 16 + lrow) * ASTRB + ks * 32) + lcolb;
                LDSM_X4(bhi[g][0], bhi[g][1], bhi[g][2], bhi[g][3], bd);
                LDSM_X4(blo[g][0], blo[g][1], blo[g][2], blo[g][3], bd + 128);
            }
            #pragma unroll
            for (int g = 0; g < 4; g++)
                #pragma unroll
                for (int hh = 0; hh < 2; hh++) {
                    const int t = 2 * g + hh;
                    MMA_BF16(oacc[t][0], oacc[t][1], oacc[t][2], oacc[t][3],
                             phi[ks][0], phi[ks][1], phi[ks][2], phi[ks][3],
                             bhi[g][hh], bhi[g][2 + hh]);
                    MMA_BF16(oacc[t][0], oacc[t][1], oacc[t][2], oacc[t][3],
                             phi[ks][0], phi[ks][1], phi[ks][2], phi[ks][3],
                             blo[g][hh], blo[g][2 + hh]);
                    MMA_BF16(oacc[t][0], oacc[t][1], oacc[t][2], oacc[t][3],
                             plo[ks][0], plo[ks][1], plo[ks][2], plo[ks][3],
                             bhi[g][hh], bhi[g][2 + hh]);
                }
        }

        if (kt < qt) {
            CP_WAIT(0);
            __syncthreads();
        }
    }

    const float inv0 = 1.0f / l0;
    const float inv1 = 1.0f / l1;
    const int r0g = q0 + rl0;
    const int r1g = q0 + rl1;
    const size_t pb0 = ((size_t)b * TSEQ + r0g) * K2 + h * HD;
    const size_t pb1 = ((size_t)b * TSEQ + r1g) * K2 + h * HD;
    #pragma unroll
    for (int t = 0; t < 8; t++) {
        const int cg = t * 8 + 2 * (lane & 3);
        const float v00 = oacc[t][0] * inv0, v01 = oacc[t][1] * inv0;
        const float v10 = oacc[t][2] * inv1, v11 = oacc[t][3] * inv1;
        const uint32_t h0 = pack_bf16(v00, v01);
        const uint32_t h1 = pack_bf16(v10, v11);
        __nv_bfloat162 h0b = *reinterpret_cast<const __nv_bfloat162*>(&h0);
        __nv_bfloat162 h1b = *reinterpret_cast<const __nv_bfloat162*>(&h1);
        const uint32_t l0p = pack_bf16(v00 - __bfloat162float(h0b.x),
                                       v01 - __bfloat162float(h0b.y));
        const uint32_t l1p = pack_bf16(v10 - __bfloat162float(h1b.x),
                                       v11 - __bfloat162float(h1b.y));
        *reinterpret_cast<uint32_t*>(&outp[pb0 + cg])        = h0;
        *reinterpret_cast<uint32_t*>(&outp[pb0 + CDIM + cg]) = l0p;
        *reinterpret_cast<uint32_t*>(&outp[pb1 + cg])        = h1;
        *reinterpret_cast<uint32_t*>(&outp[pb1 + CDIM + cg]) = l1p;
    }
}

// ---------------------------------------------------------------------------
// Launch
// ---------------------------------------------------------------------------
extern "C" void kernel_launch(void* const* d_in, const int* in_sizes, int n_in,
                              void* d_out, int out_size)
{
    const float* x     = (const float*)d_in[0];
    const float* Wqkv  = (const float*)d_in[1];
    const float* bqkv  = (const float*)d_in[2];
    const float* Wproj = (const float*)d_in[3];
    const float* bproj = (const float*)d_in[4];
    float* out = (float*)d_out;

    __nv_bfloat16 *ahat, *bqkvp, *bprojp, *qp, *kp, *vp;
    cudaGetSymbolAddress((void**)&ahat,   g_ahat);
    cudaGetSymbolAddress((void**)&bqkvp,  g_bqkv);
    cudaGetSymbolAddress((void**)&bprojp, g_bproj);
    cudaGetSymbolAddress((void**)&qp,     g_qpack);
    cudaGetSymbolAddress((void**)&kp,     g_kpack);
    cudaGetSymbolAddress((void**)&vp,     g_vpack);

    cudaFuncSetAttribute(attn_mma,
                         cudaFuncAttributeMaxDynamicSharedMemorySize, ATTN_SMEM);
    cudaFuncSetAttribute(gemm_mma,
                         cudaFuncAttributeMaxDynamicSharedMemorySize, GEMM_SMEM);
    cudaFuncSetAttribute(gemm_qkv,
                         cudaFuncAttributeMaxDynamicSharedMemorySize, GEMM_SMEM);

    // Pack weights -> [N, 2K] = [hi|lo]
    {
        dim3 bb(32, 8);
        convert_split_wT<<<dim3(THREEC / 32, CDIM / 32), bb>>>(Wqkv, bqkvp, CDIM, THREEC);
        convert_split_wT<<<dim3(CDIM / 32, CDIM / 32), bb>>>(Wproj, bprojp, CDIM, CDIM);
    }

    // 1) Pack x; QKV GEMM writes packed Q/K/V directly (prep fused)
    convert_split_act<<<(MROWS * CDIM + 255) / 256, 256>>>(x, ahat, MROWS * CDIM, CDIM);
    gemm_qkv<<<dim3(THREEC / 128, MROWS / 128), 256, GEMM_SMEM>>>(
        ahat, bqkvp, bqkv, qp, kp, vp);

    // 2) Pipelined attention -> packed proj input
    attn_mma<<<dim3(TSEQ / 64, NH, BATCH), 128, ATTN_SMEM>>>(qp, kp, vp, ahat);

    // 3) Output projection
    gemm_mma<<<dim3(CDIM / 128, MROWS / 128), 256, GEMM_SMEM>>>(
        ahat, bprojp, bproj, out, MROWS, CDIM);
}